// round 4
// baseline (speedup 1.0000x reference)
#include <cuda_runtime.h>
#include <cuda_bf16.h>
#include <math.h>
#include <stdint.h>

#define Bn  32
#define LCn 2048
#define LRn 512
#define Dn  256
#define Hn  128
#define MC  (Bn * LCn)
#define MR  (Bn * LRn)
#define NCH 8

// -------- scratch --------
static __device__ float g_E [(size_t)Bn * LCn * LRn];
static __device__ float g_ET[(size_t)Bn * LRn * LCn];
static __device__ float g_cd[(size_t)Bn * LCn * Dn];
static __device__ float g_rd[(size_t)Bn * LRn * Dn];
static __device__ float g_rsT[(size_t)Bn * Dn * LRn];
static __device__ float g_csT[(size_t)Bn * Dn * LCn];
static __device__ float g_amax[MC], g_asum[MC];
static __device__ float g_bmax[MR], g_bsum[MR];
static __device__ float g_pmax[Bn * NCH * LRn], g_psum[Bn * NCH * LRn];
static __device__ float g_W1c[Hn * 3 * Dn], g_W2c[Hn * 3 * Dn];

// ======================== helpers =============================
__device__ __forceinline__ uint32_t smem_u32(const void* p) {
    uint32_t a;
    asm("{ .reg .u64 t; cvta.to.shared.u64 t, %1; cvt.u32.u64 %0, t; }" : "=r"(a) : "l"(p));
    return a;
}

#define LDSM4(r, addr) \
    asm volatile("ldmatrix.sync.aligned.m8n8.x4.shared.b16 {%0,%1,%2,%3}, [%4];" \
        : "=r"((r)[0]), "=r"((r)[1]), "=r"((r)[2]), "=r"((r)[3]) : "r"(addr))

#define MMA_BF16(c, a, b0, b1) \
    asm volatile("mma.sync.aligned.m16n8k16.row.col.f32.bf16.bf16.f32 " \
        "{%0,%1,%2,%3}, {%4,%5,%6,%7}, {%8,%9}, {%0,%1,%2,%3};" \
        : "+f"((c)[0]), "+f"((c)[1]), "+f"((c)[2]), "+f"((c)[3]) \
        : "r"((a)[0]), "r"((a)[1]), "r"((a)[2]), "r"((a)[3]), "r"(b0), "r"(b1))

#define STS64(addr, v0, v1) \
    asm volatile("st.shared.v2.b32 [%0], {%1,%2};" :: "r"(addr), "r"(v0), "r"(v1) : "memory")

__device__ __forceinline__ void bsplit(float v, uint16_t& h, uint16_t& l) {
    __nv_bfloat16 hb = __float2bfloat16(v);
    h = __bfloat16_as_ushort(hb);
    l = __bfloat16_as_ushort(__float2bfloat16(v - __bfloat162float(hb)));
}

// smem tile layout: [128 rows][32 k] bf16, row = 64B = 4x16B units,
// unit swizzle: c16' = c16 ^ (row & 3)
__device__ __forceinline__ uint32_t toff(int row, int c16) {
    return (row << 6) + ((c16 ^ (row & 3)) << 4);
}

#define TILE_BYTES 8192
#define STAGE_B    (4 * TILE_BYTES)       // AH,AL,BH,BL
#define SM_AH 0
#define SM_AL 8192
#define SM_BH 16384
#define SM_BL 24576
#define SMEM_TOTAL (2 * STAGE_B)          // 64 KB, 2 stages

// ============================================================================
// Unified NT tensor-core GEMM: C[128,128] = A[128,K] * B[128,K]^T (bf16x3)
// MODE 0: plain.  MODE 1: A=exp(A-rmax[row]); epi *= 1/rsum[row].
// MODE 2: A = [X | Y | X*Y] (K=3*Dn); epi = relu(+bias).
// 2-stage smem double buffer, one barrier per K-chunk.
// ============================================================================
template<int MODE>
__global__ void __launch_bounds__(256, 1) k_gemm(
    const float* __restrict__ Ap, const float* __restrict__ Bp,
    const float* __restrict__ Xp, const float* __restrict__ Yp,
    const float* __restrict__ rmax, const float* __restrict__ rsum,
    const float* __restrict__ bias, float* __restrict__ Cp,
    int K, int lda, int ldb, int ldc,
    size_t aB, size_t bB, size_t cB, int sB)
{
    extern __shared__ __align__(16) uint8_t sm[];
    const uint32_t sb = smem_u32(sm);
    const int tid = threadIdx.x;
    const int z = blockIdx.z;
    const int m0 = blockIdx.x * 128, n0 = blockIdx.y * 128;
    const float* A  = Ap + (size_t)z * aB;
    const float* Bm = Bp + (size_t)z * bB;
    float* C = Cp + (size_t)z * cB;

    const int lane = tid & 31, wid = tid >> 5;
    const int wm = wid & 3, wn = wid >> 2;        // 4x2 warps: 32 rows x 64 cols
    const int gid = lane >> 2, tig = lane & 3;
    const int frow = tid >> 3, fk4 = tid & 7;

    float acc[2][8][4];
    #pragma unroll
    for (int a = 0; a < 2; a++)
        #pragma unroll
        for (int b = 0; b < 8; b++)
            #pragma unroll
            for (int c = 0; c < 4; c++) acc[a][b][c] = 0.f;

    const int S = K >> 5;
    float4 pa[4], pb[4];

    // ---- LDG of one (clamped) chunk into regs ----
    auto ldg_chunk = [&](int kc) {
        const int k0 = kc << 5;
        #pragma unroll
        for (int i = 0; i < 4; i++) {
            int row = frow + i * 32;
            if (MODE == 2) {
                int seg = k0 >> 8;
                int d = (k0 & 255) + (fk4 << 2);
                float4 x = *(const float4*)(Xp + (size_t)(m0 + row) * Dn + d);
                if (seg == 0) pa[i] = x;
                else {
                    float4 y = *(const float4*)(Yp + (size_t)(m0 + row) * Dn + d);
                    if (seg == 1) pa[i] = y;
                    else pa[i] = make_float4(x.x*y.x, x.y*y.y, x.z*y.z, x.w*y.w);
                }
            } else {
                pa[i] = *(const float4*)(A + (size_t)(m0 + row) * lda + k0 + (fk4 << 2));
            }
            pb[i] = *(const float4*)(Bm + (size_t)(n0 + row) * ldb + k0 + (fk4 << 2));
        }
    };

    // ---- convert regs + STS into given stage ----
    auto sts_chunk = [&](int buf) {
        const uint32_t tb = sb + buf * STAGE_B;
        #pragma unroll
        for (int i = 0; i < 4; i++) {
            int row = frow + i * 32;
            float4 v = pa[i];
            if (MODE == 1) {
                float rm = __ldg(rmax + (size_t)z * sB + m0 + row);
                v.x = __expf(v.x - rm); v.y = __expf(v.y - rm);
                v.z = __expf(v.z - rm); v.w = __expf(v.w - rm);
            }
            uint16_t h0,h1,h2,h3,l0,l1,l2,l3;
            bsplit(v.x,h0,l0); bsplit(v.y,h1,l1); bsplit(v.z,h2,l2); bsplit(v.w,h3,l3);
            uint32_t off = toff(row, fk4 >> 1) + ((fk4 & 1) << 3);
            STS64(tb + SM_AH + off, (uint32_t)h0 | ((uint32_t)h1 << 16),
                                    (uint32_t)h2 | ((uint32_t)h3 << 16));
            STS64(tb + SM_AL + off, (uint32_t)l0 | ((uint32_t)l1 << 16),
                                    (uint32_t)l2 | ((uint32_t)l3 << 16));
            float4 w = pb[i];
            bsplit(w.x,h0,l0); bsplit(w.y,h1,l1); bsplit(w.z,h2,l2); bsplit(w.w,h3,l3);
            STS64(tb + SM_BH + off, (uint32_t)h0 | ((uint32_t)h1 << 16),
                                    (uint32_t)h2 | ((uint32_t)h3 << 16));
            STS64(tb + SM_BL + off, (uint32_t)l0 | ((uint32_t)l1 << 16),
                                    (uint32_t)l2 | ((uint32_t)l3 << 16));
        }
    };

    // ---- prologue: stage chunk 0, prefetch chunk 1 ----
    ldg_chunk(0);
    sts_chunk(0);
    ldg_chunk(S > 1 ? 1 : 0);
    __syncthreads();

    for (int s = 0; s < S; s++) {
        // stage chunk s+1 (regs) into buf^1 — no barrier vs compute on buf
        sts_chunk((s + 1) & 1);
        // prefetch chunk s+2
        int kn = s + 2; if (kn > S - 1) kn = S - 1;
        ldg_chunk(kn);

        // ---- compute chunk s from buf s&1 ----
        const uint32_t tb = sb + (s & 1) * STAGE_B;
        #pragma unroll
        for (int kb = 0; kb < 2; kb++) {
            uint32_t ah[2][4], al[2][4];
            #pragma unroll
            for (int mb = 0; mb < 2; mb++) {
                int row = wm * 32 + mb * 16 + (lane & 15);
                uint32_t off = toff(row, kb * 2 + (lane >> 4));
                LDSM4(ah[mb], tb + SM_AH + off);
                LDSM4(al[mb], tb + SM_AL + off);
            }
            #pragma unroll
            for (int np = 0; np < 4; np++) {
                int nrow = wn * 64 + np * 16 + (lane & 7) + ((lane >> 4) << 3);
                uint32_t off = toff(nrow, kb * 2 + ((lane >> 3) & 1));
                uint32_t bh[4], bl[4];
                LDSM4(bh, tb + SM_BH + off);
                LDSM4(bl, tb + SM_BL + off);
                #pragma unroll
                for (int nb = 0; nb < 2; nb++) {
                    int n = np * 2 + nb;
                    #pragma unroll
                    for (int mb = 0; mb < 2; mb++) {
                        MMA_BF16(acc[mb][n], ah[mb], bh[nb*2], bh[nb*2+1]);
                        MMA_BF16(acc[mb][n], ah[mb], bl[nb*2], bl[nb*2+1]);
                        MMA_BF16(acc[mb][n], al[mb], bh[nb*2], bh[nb*2+1]);
                    }
                }
            }
        }
        __syncthreads();
    }

    // ---- epilogue ----
    #pragma unroll
    for (int mb = 0; mb < 2; mb++) {
        int r0 = m0 + wm * 32 + mb * 16 + gid;
        int r1 = r0 + 8;
        float s0 = 1.f, s1 = 1.f;
        if (MODE == 1) {
            s0 = 1.0f / rsum[(size_t)z * sB + r0];
            s1 = 1.0f / rsum[(size_t)z * sB + r1];
        }
        #pragma unroll
        for (int nb = 0; nb < 8; nb++) {
            int col = n0 + wn * 64 + nb * 8 + tig * 2;
            float c0 = acc[mb][nb][0], c1 = acc[mb][nb][1];
            float c2 = acc[mb][nb][2], c3 = acc[mb][nb][3];
            if (MODE == 1) { c0 *= s0; c1 *= s0; c2 *= s1; c3 *= s1; }
            if (MODE == 2) {
                float b0v = bias[col], b1v = bias[col + 1];
                c0 = fmaxf(c0 + b0v, 0.f); c1 = fmaxf(c1 + b1v, 0.f);
                c2 = fmaxf(c2 + b0v, 0.f); c3 = fmaxf(c3 + b1v, 0.f);
            }
            *(float2*)(C + (size_t)r0 * ldc + col) = make_float2(c0, c1);
            *(float2*)(C + (size_t)r1 * ldc + col) = make_float2(c2, c3);
        }
    }
}

// ============================================================================
// Batched 32x32 transpose
// ============================================================================
__global__ void k_transpose(const float* __restrict__ src, float* __restrict__ dst,
                            int rows, int cols) {
    __shared__ float t[32][33];
    int b = blockIdx.z;
    src += (size_t)b * rows * cols;
    dst += (size_t)b * rows * cols;
    int c0 = blockIdx.x * 32, r0 = blockIdx.y * 32;
    int x = threadIdx.x, y = threadIdx.y;
    #pragma unroll
    for (int i = 0; i < 32; i += 8)
        t[y + i][x] = src[(size_t)(r0 + y + i) * cols + c0 + x];
    __syncthreads();
    #pragma unroll
    for (int i = 0; i < 32; i += 8)
        dst[(size_t)(c0 + y + i) * rows + r0 + x] = t[x][y + i];
}

// ============================================================================
// Weight folding + softmax stats
// ============================================================================
__global__ void k_wcomb(const float* __restrict__ W1, const float* __restrict__ W2) {
    int i = blockIdx.x * 256 + threadIdx.x;
    if (i >= Hn * Dn) return;
    int h = i >> 8, d = i & (Dn - 1);
    const float* w1 = W1 + (size_t)h * 4 * Dn;
    g_W1c[(size_t)h * 3 * Dn + d]          = w1[d] + w1[2 * Dn + d];
    g_W1c[(size_t)h * 3 * Dn + Dn + d]     = w1[Dn + d] - w1[2 * Dn + d];
    g_W1c[(size_t)h * 3 * Dn + 2 * Dn + d] = w1[3 * Dn + d];
    const float* w2 = W2 + (size_t)h * 4 * Dn;
    g_W2c[(size_t)h * 3 * Dn + d]          = w2[d] + w2[2 * Dn + d];
    g_W2c[(size_t)h * 3 * Dn + Dn + d]     = w2[Dn + d] - w2[2 * Dn + d];
    g_W2c[(size_t)h * 3 * Dn + 2 * Dn + d] = w2[3 * Dn + d];
}

__global__ void k_alpha_stats() {
    int row  = blockIdx.x * 8 + (threadIdx.x >> 5);
    int lane = threadIdx.x & 31;
    const float* e = g_E + (size_t)row * LRn;
    float v[16], m = -1e30f;
    #pragma unroll
    for (int i = 0; i < 16; i++) { v[i] = e[lane + i * 32]; m = fmaxf(m, v[i]); }
    #pragma unroll
    for (int o = 16; o > 0; o >>= 1) m = fmaxf(m, __shfl_xor_sync(0xffffffffu, m, o));
    float s = 0.f;
    #pragma unroll
    for (int i = 0; i < 16; i++) s += __expf(v[i] - m);
    #pragma unroll
    for (int o = 16; o > 0; o >>= 1) s += __shfl_xor_sync(0xffffffffu, s, o);
    if (lane == 0) { g_amax[row] = m; g_asum[row] = s; }
}

__global__ void k_beta_part() {
    int b = blockIdx.z, ch = blockIdx.y;
    int r = blockIdx.x * 128 + threadIdx.x;
    const float* e = g_E + (size_t)b * LCn * LRn + r;
    int c0 = ch * (LCn / NCH);
    float m = -1e30f, s = 0.f;
    for (int c = 0; c < LCn / NCH; c += 4) {
        float v0 = e[(size_t)(c0 + c + 0) * LRn];
        float v1 = e[(size_t)(c0 + c + 1) * LRn];
        float v2 = e[(size_t)(c0 + c + 2) * LRn];
        float v3 = e[(size_t)(c0 + c + 3) * LRn];
        float nm = fmaxf(fmaxf(fmaxf(v0, v1), fmaxf(v2, v3)), m);
        s = s * __expf(m - nm) + __expf(v0 - nm) + __expf(v1 - nm)
                                + __expf(v2 - nm) + __expf(v3 - nm);
        m = nm;
    }
    int idx = (b * NCH + ch) * LRn + r;
    g_pmax[idx] = m; g_psum[idx] = s;
}

__global__ void k_beta_merge() {
    int idx = blockIdx.x * 256 + threadIdx.x;
    int b = idx / LRn, r = idx % LRn;
    float m = -1e30f, s = 0.f;
    #pragma unroll
    for (int ch = 0; ch < NCH; ch++) {
        int p = (b * NCH + ch) * LRn + r;
        float pm = g_pmax[p], ps = g_psum[p];
        float nm = fmaxf(m, pm);
        s = s * __expf(m - nm) + ps * __expf(pm - nm);
        m = nm;
    }
    g_bmax[idx] = m; g_bsum[idx] = s;
}

// ============================================================================
extern "C" void kernel_launch(void* const* d_in, const int* in_sizes, int n_in,
                              void* d_out, int out_size) {
    const float* cs = (const float*)d_in[0];
    const float* rs = (const float*)d_in[1];
    const float* W1 = (const float*)d_in[2];
    const float* b1 = (const float*)d_in[3];
    const float* W2 = (const float*)d_in[4];
    const float* b2 = (const float*)d_in[5];
    float* cl = (float*)d_out;
    float* rl = cl + (size_t)MC * Hn;

    float* gE;  cudaGetSymbolAddress((void**)&gE,  g_E);
    float* gET; cudaGetSymbolAddress((void**)&gET, g_ET);
    float* gcd; cudaGetSymbolAddress((void**)&gcd, g_cd);
    float* grd; cudaGetSymbolAddress((void**)&grd, g_rd);
    float* grsT; cudaGetSymbolAddress((void**)&grsT, g_rsT);
    float* gcsT; cudaGetSymbolAddress((void**)&gcsT, g_csT);
    float* gam; cudaGetSymbolAddress((void**)&gam, g_amax);
    float* gas; cudaGetSymbolAddress((void**)&gas, g_asum);
    float* gbm; cudaGetSymbolAddress((void**)&gbm, g_bmax);
    float* gbs; cudaGetSymbolAddress((void**)&gbs, g_bsum);
    float* gw1; cudaGetSymbolAddress((void**)&gw1, g_W1c);
    float* gw2; cudaGetSymbolAddress((void**)&gw2, g_W2c);

    cudaFuncSetAttribute(k_gemm<0>, cudaFuncAttributeMaxDynamicSharedMemorySize, SMEM_TOTAL);
    cudaFuncSetAttribute(k_gemm<1>, cudaFuncAttributeMaxDynamicSharedMemorySize, SMEM_TOTAL);
    cudaFuncSetAttribute(k_gemm<2>, cudaFuncAttributeMaxDynamicSharedMemorySize, SMEM_TOTAL);

    k_wcomb<<<(Hn * Dn + 255) / 256, 256>>>(W1, W2);
    k_transpose<<<dim3(8, 16, Bn), dim3(32, 8)>>>(rs, grsT, LRn, Dn);
    k_transpose<<<dim3(8, 64, Bn), dim3(32, 8)>>>(cs, gcsT, LCn, Dn);

    // E = cs * rs^T
    k_gemm<0><<<dim3(16, 4, Bn), 256, SMEM_TOTAL>>>(
        cs, rs, nullptr, nullptr, nullptr, nullptr, nullptr, gE,
        Dn, Dn, Dn, LRn,
        (size_t)LCn * Dn, (size_t)LRn * Dn, (size_t)LCn * LRn, 0);

    k_alpha_stats<<<MC / 8, 256>>>();
    k_beta_part<<<dim3(LRn / 128, NCH, Bn), 128>>>();
    k_beta_merge<<<MR / 256, 256>>>();
    k_transpose<<<dim3(16, 64, Bn), dim3(32, 8)>>>(gE, gET, LCn, LRn);

    // cd = softmax_r(E) * rs       (A = E rows + exp, B = rs^T)
    k_gemm<1><<<dim3(16, 2, Bn), 256, SMEM_TOTAL>>>(
        gE, grsT, nullptr, nullptr, gam, gas, nullptr, gcd,
        LRn, LRn, LRn, Dn,
        (size_t)LCn * LRn, (size_t)Dn * LRn, (size_t)LCn * Dn, LCn);

    // rd = softmax_c(E)^T * cs     (A = E^T rows + exp, B = cs^T)
    k_gemm<1><<<dim3(4, 2, Bn), 256, SMEM_TOTAL>>>(
        gET, gcsT, nullptr, nullptr, gbm, gbs, nullptr, grd,
        LCn, LCn, LCn, Dn,
        (size_t)LRn * LCn, (size_t)Dn * LCn, (size_t)LRn * Dn, LRn);

    // cl = relu([cs|cd|cs*cd] * W1c^T + b1)
    k_gemm<2><<<dim3(MC / 128, 1, 1), 256, SMEM_TOTAL>>>(
        nullptr, gw1, cs, gcd, nullptr, nullptr, b1, cl,
        3 * Dn, 0, 3 * Dn, Hn, 0, 0, 0, 0);

    // rl = relu([rs|rd|rs*rd] * W2c^T + b2)
    k_gemm<2><<<dim3(MR / 128, 1, 1), 256, SMEM_TOTAL>>>(
        nullptr, gw2, rs, grd, nullptr, nullptr, b2, rl,
        3 * Dn, 0, 3 * Dn, Hn, 0, 0, 0, 0);
}

// round 5
// speedup vs baseline: 1.0532x; 1.0532x over previous
#include <cuda_runtime.h>
#include <cuda_bf16.h>
#include <math.h>
#include <stdint.h>

#define Bn  32
#define LCn 2048
#define LRn 512
#define Dn  256
#define Hn  128
#define MC  (Bn * LCn)
#define MR  (Bn * LRn)
#define NCH 8

// -------- scratch --------
static __device__ float g_E [(size_t)Bn * LCn * LRn];
static __device__ float g_ET[(size_t)Bn * LRn * LCn];
static __device__ float g_cd[(size_t)Bn * LCn * Dn];
static __device__ float g_rd[(size_t)Bn * LRn * Dn];
static __device__ float g_rsT[(size_t)Bn * Dn * LRn];
static __device__ float g_csT[(size_t)Bn * Dn * LCn];
static __device__ float g_amax[MC], g_asum[MC];
static __device__ float g_bmax[MR], g_bsum[MR];
static __device__ float g_pmax[Bn * NCH * LRn], g_psum[Bn * NCH * LRn];
static __device__ float g_W1c[Hn * 3 * Dn], g_W2c[Hn * 3 * Dn];

// ======================== helpers =============================
__device__ __forceinline__ uint32_t smem_u32(const void* p) {
    uint32_t a;
    asm("{ .reg .u64 t; cvta.to.shared.u64 t, %1; cvt.u32.u64 %0, t; }" : "=r"(a) : "l"(p));
    return a;
}

#define LDSM4(r, addr) \
    asm volatile("ldmatrix.sync.aligned.m8n8.x4.shared.b16 {%0,%1,%2,%3}, [%4];" \
        : "=r"((r)[0]), "=r"((r)[1]), "=r"((r)[2]), "=r"((r)[3]) : "r"(addr))

#define MMA_BF16(c, a, b0, b1) \
    asm volatile("mma.sync.aligned.m16n8k16.row.col.f32.bf16.bf16.f32 " \
        "{%0,%1,%2,%3}, {%4,%5,%6,%7}, {%8,%9}, {%0,%1,%2,%3};" \
        : "+f"((c)[0]), "+f"((c)[1]), "+f"((c)[2]), "+f"((c)[3]) \
        : "r"((a)[0]), "r"((a)[1]), "r"((a)[2]), "r"((a)[3]), "r"(b0), "r"(b1))

#define STS64(addr, v0, v1) \
    asm volatile("st.shared.v2.b32 [%0], {%1,%2};" :: "r"(addr), "r"(v0), "r"(v1) : "memory")

__device__ __forceinline__ void bsplit(float v, uint16_t& h, uint16_t& l) {
    __nv_bfloat16 hb = __float2bfloat16(v);
    h = __bfloat16_as_ushort(hb);
    l = __bfloat16_as_ushort(__float2bfloat16(v - __bfloat162float(hb)));
}

// smem tile layout: [128 rows][32 k] bf16, row = 64B = 4x16B units,
// unit swizzle: c16' = c16 ^ (row & 3)
__device__ __forceinline__ uint32_t toff(int row, int c16) {
    return (row << 6) + ((c16 ^ (row & 3)) << 4);
}

#define TILE_BYTES 8192
#define SM_AH 0
#define SM_AL 8192
#define SM_BH 16384
#define SM_BL 24576

// ============================================================================
// Unified NT tensor-core GEMM: C[128,128] = A[128,K] * B[128,K]^T (bf16x3)
// MODE 0: plain.  MODE 1: A=exp(A-rmax[row]); epi *= 1/rsum[row].
// MODE 2: A = [X | Y | X*Y] (K=3*Dn); epi = relu(+bias).
// Single-stage smem, product-grouped MMA issue (acc reuse distance = 16).
// ============================================================================
template<int MODE>
__global__ void __launch_bounds__(256, 1) k_gemm(
    const float* __restrict__ Ap, const float* __restrict__ Bp,
    const float* __restrict__ Xp, const float* __restrict__ Yp,
    const float* __restrict__ rmax, const float* __restrict__ rsum,
    const float* __restrict__ bias, float* __restrict__ Cp,
    int K, int lda, int ldb, int ldc,
    size_t aB, size_t bB, size_t cB, int sB)
{
    __shared__ __align__(16) uint8_t sm[4 * TILE_BYTES];
    const uint32_t sb = smem_u32(sm);
    const int tid = threadIdx.x;
    const int z = blockIdx.z;
    const int m0 = blockIdx.x * 128, n0 = blockIdx.y * 128;
    const float* A  = Ap + (size_t)z * aB;
    const float* Bm = Bp + (size_t)z * bB;
    float* C = Cp + (size_t)z * cB;

    const int lane = tid & 31, wid = tid >> 5;
    const int wm = wid & 3, wn = wid >> 2;        // 4x2 warps: 32 rows x 64 cols
    const int gid = lane >> 2, tig = lane & 3;
    const int frow = tid >> 3, fk4 = tid & 7;

    float acc[2][8][4];
    #pragma unroll
    for (int a = 0; a < 2; a++)
        #pragma unroll
        for (int b = 0; b < 8; b++)
            #pragma unroll
            for (int c = 0; c < 4; c++) acc[a][b][c] = 0.f;

    const int S = K >> 5;
    float4 pa[4], pb[4];

    // ---- prefetch chunk 0 ----
    {
        #pragma unroll
        for (int i = 0; i < 4; i++) {
            int row = frow + i * 32;
            if (MODE == 2) {
                float4 x = *(const float4*)(Xp + (size_t)(m0 + row) * Dn + (fk4 << 2));
                pa[i] = x;
            } else {
                pa[i] = *(const float4*)(A + (size_t)(m0 + row) * lda + (fk4 << 2));
            }
            pb[i] = *(const float4*)(Bm + (size_t)(n0 + row) * ldb + (fk4 << 2));
        }
    }

    for (int s = 0; s < S; s++) {
        const int k0 = s << 5;
        // ---- convert + STS ----
        #pragma unroll
        for (int i = 0; i < 4; i++) {
            int row = frow + i * 32;
            float4 v = pa[i];
            if (MODE == 1) {
                float rm = __ldg(rmax + (size_t)z * sB + m0 + row);
                v.x = __expf(v.x - rm); v.y = __expf(v.y - rm);
                v.z = __expf(v.z - rm); v.w = __expf(v.w - rm);
            }
            uint16_t h0,h1,h2,h3,l0,l1,l2,l3;
            bsplit(v.x,h0,l0); bsplit(v.y,h1,l1); bsplit(v.z,h2,l2); bsplit(v.w,h3,l3);
            uint32_t off = toff(row, fk4 >> 1) + ((fk4 & 1) << 3);
            STS64(sb + SM_AH + off, (uint32_t)h0 | ((uint32_t)h1 << 16),
                                    (uint32_t)h2 | ((uint32_t)h3 << 16));
            STS64(sb + SM_AL + off, (uint32_t)l0 | ((uint32_t)l1 << 16),
                                    (uint32_t)l2 | ((uint32_t)l3 << 16));
            float4 w = pb[i];
            bsplit(w.x,h0,l0); bsplit(w.y,h1,l1); bsplit(w.z,h2,l2); bsplit(w.w,h3,l3);
            STS64(sb + SM_BH + off, (uint32_t)h0 | ((uint32_t)h1 << 16),
                                    (uint32_t)h2 | ((uint32_t)h3 << 16));
            STS64(sb + SM_BL + off, (uint32_t)l0 | ((uint32_t)l1 << 16),
                                    (uint32_t)l2 | ((uint32_t)l3 << 16));
        }
        __syncthreads();

        // ---- prefetch next chunk ----
        if (s + 1 < S) {
            const int kn = k0 + 32;
            #pragma unroll
            for (int i = 0; i < 4; i++) {
                int row = frow + i * 32;
                if (MODE == 2) {
                    int seg = kn >> 8;
                    int d = (kn & 255) + (fk4 << 2);
                    float4 x = *(const float4*)(Xp + (size_t)(m0 + row) * Dn + d);
                    if (seg == 0) pa[i] = x;
                    else {
                        float4 y = *(const float4*)(Yp + (size_t)(m0 + row) * Dn + d);
                        if (seg == 1) pa[i] = y;
                        else pa[i] = make_float4(x.x*y.x, x.y*y.y, x.z*y.z, x.w*y.w);
                    }
                } else {
                    pa[i] = *(const float4*)(A + (size_t)(m0 + row) * lda + kn + (fk4 << 2));
                }
                pb[i] = *(const float4*)(Bm + (size_t)(n0 + row) * ldb + kn + (fk4 << 2));
            }
        }

        // ---- compute 2 x k16 steps, product-grouped MMA issue ----
        #pragma unroll
        for (int kb = 0; kb < 2; kb++) {
            uint32_t ah[2][4], al[2][4];
            #pragma unroll
            for (int mb = 0; mb < 2; mb++) {
                int row = wm * 32 + mb * 16 + (lane & 15);
                uint32_t off = toff(row, kb * 2 + (lane >> 4));
                LDSM4(ah[mb], sb + SM_AH + off);
                LDSM4(al[mb], sb + SM_AL + off);
            }
            uint32_t bh[4][4], bl[4][4];
            #pragma unroll
            for (int np = 0; np < 4; np++) {
                int nrow = wn * 64 + np * 16 + (lane & 7) + ((lane >> 4) << 3);
                uint32_t off = toff(nrow, kb * 2 + ((lane >> 3) & 1));
                LDSM4(bh[np], sb + SM_BH + off);
                LDSM4(bl[np], sb + SM_BL + off);
            }
            // HH: 16 independent MMAs
            #pragma unroll
            for (int np = 0; np < 4; np++)
                #pragma unroll
                for (int nb = 0; nb < 2; nb++)
                    #pragma unroll
                    for (int mb = 0; mb < 2; mb++)
                        MMA_BF16(acc[mb][np*2+nb], ah[mb], bh[np][nb*2], bh[np][nb*2+1]);
            // HL
            #pragma unroll
            for (int np = 0; np < 4; np++)
                #pragma unroll
                for (int nb = 0; nb < 2; nb++)
                    #pragma unroll
                    for (int mb = 0; mb < 2; mb++)
                        MMA_BF16(acc[mb][np*2+nb], ah[mb], bl[np][nb*2], bl[np][nb*2+1]);
            // LH
            #pragma unroll
            for (int np = 0; np < 4; np++)
                #pragma unroll
                for (int nb = 0; nb < 2; nb++)
                    #pragma unroll
                    for (int mb = 0; mb < 2; mb++)
                        MMA_BF16(acc[mb][np*2+nb], al[mb], bh[np][nb*2], bh[np][nb*2+1]);
        }
        __syncthreads();
    }

    // ---- epilogue ----
    #pragma unroll
    for (int mb = 0; mb < 2; mb++) {
        int r0 = m0 + wm * 32 + mb * 16 + gid;
        int r1 = r0 + 8;
        float s0 = 1.f, s1 = 1.f;
        if (MODE == 1) {
            s0 = 1.0f / rsum[(size_t)z * sB + r0];
            s1 = 1.0f / rsum[(size_t)z * sB + r1];
        }
        #pragma unroll
        for (int nb = 0; nb < 8; nb++) {
            int col = n0 + wn * 64 + nb * 8 + tig * 2;
            float c0 = acc[mb][nb][0], c1 = acc[mb][nb][1];
            float c2 = acc[mb][nb][2], c3 = acc[mb][nb][3];
            if (MODE == 1) { c0 *= s0; c1 *= s0; c2 *= s1; c3 *= s1; }
            if (MODE == 2) {
                float b0v = bias[col], b1v = bias[col + 1];
                c0 = fmaxf(c0 + b0v, 0.f); c1 = fmaxf(c1 + b1v, 0.f);
                c2 = fmaxf(c2 + b0v, 0.f); c3 = fmaxf(c3 + b1v, 0.f);
            }
            *(float2*)(C + (size_t)r0 * ldc + col) = make_float2(c0, c1);
            *(float2*)(C + (size_t)r1 * ldc + col) = make_float2(c2, c3);
        }
    }
}

// ============================================================================
// Batched 32x32 transpose
// ============================================================================
__global__ void k_transpose(const float* __restrict__ src, float* __restrict__ dst,
                            int rows, int cols) {
    __shared__ float t[32][33];
    int b = blockIdx.z;
    src += (size_t)b * rows * cols;
    dst += (size_t)b * rows * cols;
    int c0 = blockIdx.x * 32, r0 = blockIdx.y * 32;
    int x = threadIdx.x, y = threadIdx.y;
    #pragma unroll
    for (int i = 0; i < 32; i += 8)
        t[y + i][x] = src[(size_t)(r0 + y + i) * cols + c0 + x];
    __syncthreads();
    #pragma unroll
    for (int i = 0; i < 32; i += 8)
        dst[(size_t)(c0 + y + i) * rows + r0 + x] = t[x][y + i];
}

// ============================================================================
// Weight folding + softmax stats
// ============================================================================
__global__ void k_wcomb(const float* __restrict__ W1, const float* __restrict__ W2) {
    int i = blockIdx.x * 256 + threadIdx.x;
    if (i >= Hn * Dn) return;
    int h = i >> 8, d = i & (Dn - 1);
    const float* w1 = W1 + (size_t)h * 4 * Dn;
    g_W1c[(size_t)h * 3 * Dn + d]          = w1[d] + w1[2 * Dn + d];
    g_W1c[(size_t)h * 3 * Dn + Dn + d]     = w1[Dn + d] - w1[2 * Dn + d];
    g_W1c[(size_t)h * 3 * Dn + 2 * Dn + d] = w1[3 * Dn + d];
    const float* w2 = W2 + (size_t)h * 4 * Dn;
    g_W2c[(size_t)h * 3 * Dn + d]          = w2[d] + w2[2 * Dn + d];
    g_W2c[(size_t)h * 3 * Dn + Dn + d]     = w2[Dn + d] - w2[2 * Dn + d];
    g_W2c[(size_t)h * 3 * Dn + 2 * Dn + d] = w2[3 * Dn + d];
}

__global__ void k_alpha_stats() {
    int row  = blockIdx.x * 8 + (threadIdx.x >> 5);
    int lane = threadIdx.x & 31;
    const float* e = g_E + (size_t)row * LRn;
    float v[16], m = -1e30f;
    #pragma unroll
    for (int i = 0; i < 16; i++) { v[i] = e[lane + i * 32]; m = fmaxf(m, v[i]); }
    #pragma unroll
    for (int o = 16; o > 0; o >>= 1) m = fmaxf(m, __shfl_xor_sync(0xffffffffu, m, o));
    float s = 0.f;
    #pragma unroll
    for (int i = 0; i < 16; i++) s += __expf(v[i] - m);
    #pragma unroll
    for (int o = 16; o > 0; o >>= 1) s += __shfl_xor_sync(0xffffffffu, s, o);
    if (lane == 0) { g_amax[row] = m; g_asum[row] = s; }
}

__global__ void k_beta_part() {
    int b = blockIdx.z, ch = blockIdx.y;
    int r = blockIdx.x * 128 + threadIdx.x;
    const float* e = g_E + (size_t)b * LCn * LRn + r;
    int c0 = ch * (LCn / NCH);
    float m = -1e30f, s = 0.f;
    for (int c = 0; c < LCn / NCH; c += 4) {
        float v0 = e[(size_t)(c0 + c + 0) * LRn];
        float v1 = e[(size_t)(c0 + c + 1) * LRn];
        float v2 = e[(size_t)(c0 + c + 2) * LRn];
        float v3 = e[(size_t)(c0 + c + 3) * LRn];
        float nm = fmaxf(fmaxf(fmaxf(v0, v1), fmaxf(v2, v3)), m);
        s = s * __expf(m - nm) + __expf(v0 - nm) + __expf(v1 - nm)
                                + __expf(v2 - nm) + __expf(v3 - nm);
        m = nm;
    }
    int idx = (b * NCH + ch) * LRn + r;
    g_pmax[idx] = m; g_psum[idx] = s;
}

__global__ void k_beta_merge() {
    int idx = blockIdx.x * 256 + threadIdx.x;
    int b = idx / LRn, r = idx % LRn;
    float m = -1e30f, s = 0.f;
    #pragma unroll
    for (int ch = 0; ch < NCH; ch++) {
        int p = (b * NCH + ch) * LRn + r;
        float pm = g_pmax[p], ps = g_psum[p];
        float nm = fmaxf(m, pm);
        s = s * __expf(m - nm) + ps * __expf(pm - nm);
        m = nm;
    }
    g_bmax[idx] = m; g_bsum[idx] = s;
}

// ============================================================================
extern "C" void kernel_launch(void* const* d_in, const int* in_sizes, int n_in,
                              void* d_out, int out_size) {
    const float* cs = (const float*)d_in[0];
    const float* rs = (const float*)d_in[1];
    const float* W1 = (const float*)d_in[2];
    const float* b1 = (const float*)d_in[3];
    const float* W2 = (const float*)d_in[4];
    const float* b2 = (const float*)d_in[5];
    float* cl = (float*)d_out;
    float* rl = cl + (size_t)MC * Hn;

    float* gE;  cudaGetSymbolAddress((void**)&gE,  g_E);
    float* gET; cudaGetSymbolAddress((void**)&gET, g_ET);
    float* gcd; cudaGetSymbolAddress((void**)&gcd, g_cd);
    float* grd; cudaGetSymbolAddress((void**)&grd, g_rd);
    float* grsT; cudaGetSymbolAddress((void**)&grsT, g_rsT);
    float* gcsT; cudaGetSymbolAddress((void**)&gcsT, g_csT);
    float* gam; cudaGetSymbolAddress((void**)&gam, g_amax);
    float* gas; cudaGetSymbolAddress((void**)&gas, g_asum);
    float* gbm; cudaGetSymbolAddress((void**)&gbm, g_bmax);
    float* gbs; cudaGetSymbolAddress((void**)&gbs, g_bsum);
    float* gw1; cudaGetSymbolAddress((void**)&gw1, g_W1c);
    float* gw2; cudaGetSymbolAddress((void**)&gw2, g_W2c);

    k_wcomb<<<(Hn * Dn + 255) / 256, 256>>>(W1, W2);
    k_transpose<<<dim3(8, 16, Bn), dim3(32, 8)>>>(rs, grsT, LRn, Dn);
    k_transpose<<<dim3(8, 64, Bn), dim3(32, 8)>>>(cs, gcsT, LCn, Dn);

    // E = cs * rs^T
    k_gemm<0><<<dim3(16, 4, Bn), 256>>>(
        cs, rs, nullptr, nullptr, nullptr, nullptr, nullptr, gE,
        Dn, Dn, Dn, LRn,
        (size_t)LCn * Dn, (size_t)LRn * Dn, (size_t)LCn * LRn, 0);

    k_alpha_stats<<<MC / 8, 256>>>();
    k_beta_part<<<dim3(LRn / 128, NCH, Bn), 128>>>();
    k_beta_merge<<<MR / 256, 256>>>();
    k_transpose<<<dim3(16, 64, Bn), dim3(32, 8)>>>(gE, gET, LCn, LRn);

    // cd = softmax_r(E) * rs       (A = E rows + exp, B = rs^T)
    k_gemm<1><<<dim3(16, 2, Bn), 256>>>(
        gE, grsT, nullptr, nullptr, gam, gas, nullptr, gcd,
        LRn, LRn, LRn, Dn,
        (size_t)LCn * LRn, (size_t)Dn * LRn, (size_t)LCn * Dn, LCn);

    // rd = softmax_c(E)^T * cs     (A = E^T rows + exp, B = cs^T)
    k_gemm<1><<<dim3(4, 2, Bn), 256>>>(
        gET, gcsT, nullptr, nullptr, gbm, gbs, nullptr, grd,
        LCn, LCn, LCn, Dn,
        (size_t)LRn * LCn, (size_t)Dn * LCn, (size_t)LRn * Dn, LRn);

    // cl = relu([cs|cd|cs*cd] * W1c^T + b1)
    k_gemm<2><<<dim3(MC / 128, 1, 1), 256>>>(
        nullptr, gw1, cs, gcd, nullptr, nullptr, b1, cl,
        3 * Dn, 0, 3 * Dn, Hn, 0, 0, 0, 0);

    // rl = relu([rs|rd|rs*rd] * W2c^T + b2)
    k_gemm<2><<<dim3(MR / 128, 1, 1), 256>>>(
        nullptr, gw2, rs, grd, nullptr, nullptr, b2, rl,
        3 * Dn, 0, 3 * Dn, Hn, 0, 0, 0, 0);
}

// round 6
// speedup vs baseline: 1.1340x; 1.0767x over previous
#include <cuda_runtime.h>
#include <cuda_bf16.h>
#include <math.h>
#include <stdint.h>

#define Bn  32
#define LCn 2048
#define LRn 512
#define Dn  256
#define Hn  128
#define MC  (Bn * LCn)
#define MR  (Bn * LRn)
#define NCH 8

// -------- scratch --------
static __device__ float g_E [(size_t)Bn * LCn * LRn];
static __device__ float g_ET[(size_t)Bn * LRn * LCn];
static __device__ float g_cd[(size_t)Bn * LCn * Dn];
static __device__ float g_rd[(size_t)Bn * LRn * Dn];
static __device__ float g_rsT[(size_t)Bn * Dn * LRn];
static __device__ float g_csT[(size_t)Bn * Dn * LCn];
static __device__ float g_amax[MC], g_asum[MC];
static __device__ float g_bmax[MR], g_bsum[MR];
static __device__ float g_pmax[Bn * NCH * LRn], g_psum[Bn * NCH * LRn];
static __device__ float g_W1c[Hn * 3 * Dn], g_W2c[Hn * 3 * Dn];

// ======================== helpers =============================
__device__ __forceinline__ uint32_t smem_u32(const void* p) {
    uint32_t a;
    asm("{ .reg .u64 t; cvta.to.shared.u64 t, %1; cvt.u32.u64 %0, t; }" : "=r"(a) : "l"(p));
    return a;
}

#define LDSM4(r, addr) \
    asm volatile("ldmatrix.sync.aligned.m8n8.x4.shared.b16 {%0,%1,%2,%3}, [%4];" \
        : "=r"((r)[0]), "=r"((r)[1]), "=r"((r)[2]), "=r"((r)[3]) : "r"(addr))

#define MMA_BF16(c, a, b0, b1) \
    asm volatile("mma.sync.aligned.m16n8k16.row.col.f32.bf16.bf16.f32 " \
        "{%0,%1,%2,%3}, {%4,%5,%6,%7}, {%8,%9}, {%0,%1,%2,%3};" \
        : "+f"((c)[0]), "+f"((c)[1]), "+f"((c)[2]), "+f"((c)[3]) \
        : "r"((a)[0]), "r"((a)[1]), "r"((a)[2]), "r"((a)[3]), "r"(b0), "r"(b1))

#define STS64(addr, v0, v1) \
    asm volatile("st.shared.v2.b32 [%0], {%1,%2};" :: "r"(addr), "r"(v0), "r"(v1) : "memory")

__device__ __forceinline__ void bsplit(float v, uint16_t& h, uint16_t& l) {
    __nv_bfloat16 hb = __float2bfloat16(v);
    h = __bfloat16_as_ushort(hb);
    l = __bfloat16_as_ushort(__float2bfloat16(v - __bfloat162float(hb)));
}

// smem tile layout: [rows][32 k] bf16, row = 64B = 4x16B units,
// unit swizzle: c16' = c16 ^ (row & 3)
__device__ __forceinline__ uint32_t toff(int row, int c16) {
    return (row << 6) + ((c16 ^ (row & 3)) << 4);
}

// A tile 128x32 bf16 = 8192 B (x2 for H/L); B tile 64x32 bf16 = 4096 B (x2)
#define SM_AH 0
#define SM_AL 8192
#define SM_BH 16384
#define SM_BL 20480
#define SMEM_SZ 24576

// ============================================================================
// Unified NT tensor-core GEMM: C[128,64] = A[128,K] * B[64,K]^T (bf16x3)
// MODE 0: plain.  MODE 1: A=exp(A-rmax[row]); epi *= 1/rsum[row].
// MODE 2: A = [X | Y | X*Y] (K=3*Dn); epi = relu(+bias).
// 128x64 CTA tile, 8 warps (4m x 2n), 2 CTAs/SM.
// ============================================================================
template<int MODE>
__global__ void __launch_bounds__(256, 2) k_gemm(
    const float* __restrict__ Ap, const float* __restrict__ Bp,
    const float* __restrict__ Xp, const float* __restrict__ Yp,
    const float* __restrict__ rmax, const float* __restrict__ rsum,
    const float* __restrict__ bias, float* __restrict__ Cp,
    int K, int lda, int ldb, int ldc,
    size_t aB, size_t bB, size_t cB, int sB)
{
    __shared__ __align__(16) uint8_t sm[SMEM_SZ];
    const uint32_t sb = smem_u32(sm);
    const int tid = threadIdx.x;
    const int z = blockIdx.z;
    const int m0 = blockIdx.x * 128, n0 = blockIdx.y * 64;
    const float* A  = Ap + (size_t)z * aB;
    const float* Bm = Bp + (size_t)z * bB;
    float* C = Cp + (size_t)z * cB;

    const int lane = tid & 31, wid = tid >> 5;
    const int wm = wid & 3, wn = wid >> 2;        // 4x2 warps: 32 rows x 32 cols
    const int gid = lane >> 2, tig = lane & 3;
    const int frow = tid >> 3, fk4 = tid & 7;     // A fill: 128 rows x 8 k4
    const int brow = tid >> 3, bk4 = tid & 7;     // B fill rows 0..63 via i<2

    float acc[2][4][4];
    #pragma unroll
    for (int a = 0; a < 2; a++)
        #pragma unroll
        for (int b = 0; b < 4; b++)
            #pragma unroll
            for (int c = 0; c < 4; c++) acc[a][b][c] = 0.f;

    const int S = K >> 5;
    float4 pa[4], pb[2];

    // ---- prefetch chunk 0 ----
    #pragma unroll
    for (int i = 0; i < 4; i++) {
        int row = frow + i * 32;
        if (MODE == 2)
            pa[i] = *(const float4*)(Xp + (size_t)(m0 + row) * Dn + (fk4 << 2));
        else
            pa[i] = *(const float4*)(A + (size_t)(m0 + row) * lda + (fk4 << 2));
    }
    #pragma unroll
    for (int i = 0; i < 2; i++) {
        int row = brow + i * 32;
        if (row < 64)
            pb[i] = *(const float4*)(Bm + (size_t)(n0 + row) * ldb + (bk4 << 2));
    }

    for (int s = 0; s < S; s++) {
        const int k0 = s << 5;
        // ---- convert + STS ----
        #pragma unroll
        for (int i = 0; i < 4; i++) {
            int row = frow + i * 32;
            float4 v = pa[i];
            if (MODE == 1) {
                float rm = __ldg(rmax + (size_t)z * sB + m0 + row);
                v.x = __expf(v.x - rm); v.y = __expf(v.y - rm);
                v.z = __expf(v.z - rm); v.w = __expf(v.w - rm);
            }
            uint16_t h0,h1,h2,h3,l0,l1,l2,l3;
            bsplit(v.x,h0,l0); bsplit(v.y,h1,l1); bsplit(v.z,h2,l2); bsplit(v.w,h3,l3);
            uint32_t off = toff(row, fk4 >> 1) + ((fk4 & 1) << 3);
            STS64(sb + SM_AH + off, (uint32_t)h0 | ((uint32_t)h1 << 16),
                                    (uint32_t)h2 | ((uint32_t)h3 << 16));
            STS64(sb + SM_AL + off, (uint32_t)l0 | ((uint32_t)l1 << 16),
                                    (uint32_t)l2 | ((uint32_t)l3 << 16));
        }
        #pragma unroll
        for (int i = 0; i < 2; i++) {
            int row = brow + i * 32;
            if (row < 64) {
                float4 w = pb[i];
                uint16_t h0,h1,h2,h3,l0,l1,l2,l3;
                bsplit(w.x,h0,l0); bsplit(w.y,h1,l1); bsplit(w.z,h2,l2); bsplit(w.w,h3,l3);
                uint32_t off = toff(row, bk4 >> 1) + ((bk4 & 1) << 3);
                STS64(sb + SM_BH + off, (uint32_t)h0 | ((uint32_t)h1 << 16),
                                        (uint32_t)h2 | ((uint32_t)h3 << 16));
                STS64(sb + SM_BL + off, (uint32_t)l0 | ((uint32_t)l1 << 16),
                                        (uint32_t)l2 | ((uint32_t)l3 << 16));
            }
        }
        __syncthreads();

        // ---- prefetch next chunk ----
        if (s + 1 < S) {
            const int kn = k0 + 32;
            #pragma unroll
            for (int i = 0; i < 4; i++) {
                int row = frow + i * 32;
                if (MODE == 2) {
                    int seg = kn >> 8;
                    int d = (kn & 255) + (fk4 << 2);
                    float4 x = *(const float4*)(Xp + (size_t)(m0 + row) * Dn + d);
                    if (seg == 0) pa[i] = x;
                    else {
                        float4 y = *(const float4*)(Yp + (size_t)(m0 + row) * Dn + d);
                        if (seg == 1) pa[i] = y;
                        else pa[i] = make_float4(x.x*y.x, x.y*y.y, x.z*y.z, x.w*y.w);
                    }
                } else {
                    pa[i] = *(const float4*)(A + (size_t)(m0 + row) * lda + kn + (fk4 << 2));
                }
            }
            #pragma unroll
            for (int i = 0; i < 2; i++) {
                int row = brow + i * 32;
                if (row < 64)
                    pb[i] = *(const float4*)(Bm + (size_t)(n0 + row) * ldb + kn + (bk4 << 2));
            }
        }

        // ---- compute 2 x k16 steps ----
        #pragma unroll
        for (int kb = 0; kb < 2; kb++) {
            uint32_t ah[2][4], al[2][4];
            #pragma unroll
            for (int mb = 0; mb < 2; mb++) {
                int row = wm * 32 + mb * 16 + (lane & 15);
                uint32_t off = toff(row, kb * 2 + (lane >> 4));
                LDSM4(ah[mb], sb + SM_AH + off);
                LDSM4(al[mb], sb + SM_AL + off);
            }
            uint32_t bh[2][4], bl[2][4];
            #pragma unroll
            for (int np = 0; np < 2; np++) {
                int nrow = wn * 32 + np * 16 + (lane & 7) + ((lane >> 4) << 3);
                uint32_t off = toff(nrow, kb * 2 + ((lane >> 3) & 1));
                LDSM4(bh[np], sb + SM_BH + off);
                LDSM4(bl[np], sb + SM_BL + off);
            }
            // HH
            #pragma unroll
            for (int np = 0; np < 2; np++)
                #pragma unroll
                for (int nb = 0; nb < 2; nb++)
                    #pragma unroll
                    for (int mb = 0; mb < 2; mb++)
                        MMA_BF16(acc[mb][np*2+nb], ah[mb], bh[np][nb*2], bh[np][nb*2+1]);
            // HL
            #pragma unroll
            for (int np = 0; np < 2; np++)
                #pragma unroll
                for (int nb = 0; nb < 2; nb++)
                    #pragma unroll
                    for (int mb = 0; mb < 2; mb++)
                        MMA_BF16(acc[mb][np*2+nb], ah[mb], bl[np][nb*2], bl[np][nb*2+1]);
            // LH
            #pragma unroll
            for (int np = 0; np < 2; np++)
                #pragma unroll
                for (int nb = 0; nb < 2; nb++)
                    #pragma unroll
                    for (int mb = 0; mb < 2; mb++)
                        MMA_BF16(acc[mb][np*2+nb], al[mb], bh[np][nb*2], bh[np][nb*2+1]);
        }
        __syncthreads();
    }

    // ---- epilogue ----
    #pragma unroll
    for (int mb = 0; mb < 2; mb++) {
        int r0 = m0 + wm * 32 + mb * 16 + gid;
        int r1 = r0 + 8;
        float s0 = 1.f, s1 = 1.f;
        if (MODE == 1) {
            s0 = 1.0f / rsum[(size_t)z * sB + r0];
            s1 = 1.0f / rsum[(size_t)z * sB + r1];
        }
        #pragma unroll
        for (int nb = 0; nb < 4; nb++) {
            int col = n0 + wn * 32 + nb * 8 + tig * 2;
            float c0 = acc[mb][nb][0], c1 = acc[mb][nb][1];
            float c2 = acc[mb][nb][2], c3 = acc[mb][nb][3];
            if (MODE == 1) { c0 *= s0; c1 *= s0; c2 *= s1; c3 *= s1; }
            if (MODE == 2) {
                float b0v = bias[col], b1v = bias[col + 1];
                c0 = fmaxf(c0 + b0v, 0.f); c1 = fmaxf(c1 + b1v, 0.f);
                c2 = fmaxf(c2 + b0v, 0.f); c3 = fmaxf(c3 + b1v, 0.f);
            }
            *(float2*)(C + (size_t)r0 * ldc + col) = make_float2(c0, c1);
            *(float2*)(C + (size_t)r1 * ldc + col) = make_float2(c2, c3);
        }
    }
}

// ============================================================================
// Batched 32x32 transpose
// ============================================================================
__global__ void k_transpose(const float* __restrict__ src, float* __restrict__ dst,
                            int rows, int cols) {
    __shared__ float t[32][33];
    int b = blockIdx.z;
    src += (size_t)b * rows * cols;
    dst += (size_t)b * rows * cols;
    int c0 = blockIdx.x * 32, r0 = blockIdx.y * 32;
    int x = threadIdx.x, y = threadIdx.y;
    #pragma unroll
    for (int i = 0; i < 32; i += 8)
        t[y + i][x] = src[(size_t)(r0 + y + i) * cols + c0 + x];
    __syncthreads();
    #pragma unroll
    for (int i = 0; i < 32; i += 8)
        dst[(size_t)(c0 + y + i) * rows + r0 + x] = t[x][y + i];
}

// ============================================================================
// Weight folding + softmax stats
// ============================================================================
__global__ void k_wcomb(const float* __restrict__ W1, const float* __restrict__ W2) {
    int i = blockIdx.x * 256 + threadIdx.x;
    if (i >= Hn * Dn) return;
    int h = i >> 8, d = i & (Dn - 1);
    const float* w1 = W1 + (size_t)h * 4 * Dn;
    g_W1c[(size_t)h * 3 * Dn + d]          = w1[d] + w1[2 * Dn + d];
    g_W1c[(size_t)h * 3 * Dn + Dn + d]     = w1[Dn + d] - w1[2 * Dn + d];
    g_W1c[(size_t)h * 3 * Dn + 2 * Dn + d] = w1[3 * Dn + d];
    const float* w2 = W2 + (size_t)h * 4 * Dn;
    g_W2c[(size_t)h * 3 * Dn + d]          = w2[d] + w2[2 * Dn + d];
    g_W2c[(size_t)h * 3 * Dn + Dn + d]     = w2[Dn + d] - w2[2 * Dn + d];
    g_W2c[(size_t)h * 3 * Dn + 2 * Dn + d] = w2[3 * Dn + d];
}

__global__ void k_alpha_stats() {
    int row  = blockIdx.x * 8 + (threadIdx.x >> 5);
    int lane = threadIdx.x & 31;
    const float* e = g_E + (size_t)row * LRn;
    float v[16], m = -1e30f;
    #pragma unroll
    for (int i = 0; i < 16; i++) { v[i] = e[lane + i * 32]; m = fmaxf(m, v[i]); }
    #pragma unroll
    for (int o = 16; o > 0; o >>= 1) m = fmaxf(m, __shfl_xor_sync(0xffffffffu, m, o));
    float s = 0.f;
    #pragma unroll
    for (int i = 0; i < 16; i++) s += __expf(v[i] - m);
    #pragma unroll
    for (int o = 16; o > 0; o >>= 1) s += __shfl_xor_sync(0xffffffffu, s, o);
    if (lane == 0) { g_amax[row] = m; g_asum[row] = s; }
}

__global__ void k_beta_part() {
    int b = blockIdx.z, ch = blockIdx.y;
    int r = blockIdx.x * 128 + threadIdx.x;
    const float* e = g_E + (size_t)b * LCn * LRn + r;
    int c0 = ch * (LCn / NCH);
    float m = -1e30f, s = 0.f;
    for (int c = 0; c < LCn / NCH; c += 4) {
        float v0 = e[(size_t)(c0 + c + 0) * LRn];
        float v1 = e[(size_t)(c0 + c + 1) * LRn];
        float v2 = e[(size_t)(c0 + c + 2) * LRn];
        float v3 = e[(size_t)(c0 + c + 3) * LRn];
        float nm = fmaxf(fmaxf(fmaxf(v0, v1), fmaxf(v2, v3)), m);
        s = s * __expf(m - nm) + __expf(v0 - nm) + __expf(v1 - nm)
                                + __expf(v2 - nm) + __expf(v3 - nm);
        m = nm;
    }
    int idx = (b * NCH + ch) * LRn + r;
    g_pmax[idx] = m; g_psum[idx] = s;
}

__global__ void k_beta_merge() {
    int idx = blockIdx.x * 256 + threadIdx.x;
    int b = idx / LRn, r = idx % LRn;
    float m = -1e30f, s = 0.f;
    #pragma unroll
    for (int ch = 0; ch < NCH; ch++) {
        int p = (b * NCH + ch) * LRn + r;
        float pm = g_pmax[p], ps = g_psum[p];
        float nm = fmaxf(m, pm);
        s = s * __expf(m - nm) + ps * __expf(pm - nm);
        m = nm;
    }
    g_bmax[idx] = m; g_bsum[idx] = s;
}

// ============================================================================
extern "C" void kernel_launch(void* const* d_in, const int* in_sizes, int n_in,
                              void* d_out, int out_size) {
    const float* cs = (const float*)d_in[0];
    const float* rs = (const float*)d_in[1];
    const float* W1 = (const float*)d_in[2];
    const float* b1 = (const float*)d_in[3];
    const float* W2 = (const float*)d_in[4];
    const float* b2 = (const float*)d_in[5];
    float* cl = (float*)d_out;
    float* rl = cl + (size_t)MC * Hn;

    float* gE;  cudaGetSymbolAddress((void**)&gE,  g_E);
    float* gET; cudaGetSymbolAddress((void**)&gET, g_ET);
    float* gcd; cudaGetSymbolAddress((void**)&gcd, g_cd);
    float* grd; cudaGetSymbolAddress((void**)&grd, g_rd);
    float* grsT; cudaGetSymbolAddress((void**)&grsT, g_rsT);
    float* gcsT; cudaGetSymbolAddress((void**)&gcsT, g_csT);
    float* gam; cudaGetSymbolAddress((void**)&gam, g_amax);
    float* gas; cudaGetSymbolAddress((void**)&gas, g_asum);
    float* gbm; cudaGetSymbolAddress((void**)&gbm, g_bmax);
    float* gbs; cudaGetSymbolAddress((void**)&gbs, g_bsum);
    float* gw1; cudaGetSymbolAddress((void**)&gw1, g_W1c);
    float* gw2; cudaGetSymbolAddress((void**)&gw2, g_W2c);

    k_wcomb<<<(Hn * Dn + 255) / 256, 256>>>(W1, W2);
    k_transpose<<<dim3(8, 16, Bn), dim3(32, 8)>>>(rs, grsT, LRn, Dn);
    k_transpose<<<dim3(8, 64, Bn), dim3(32, 8)>>>(cs, gcsT, LCn, Dn);

    // E = cs * rs^T
    k_gemm<0><<<dim3(16, 8, Bn), 256>>>(
        cs, rs, nullptr, nullptr, nullptr, nullptr, nullptr, gE,
        Dn, Dn, Dn, LRn,
        (size_t)LCn * Dn, (size_t)LRn * Dn, (size_t)LCn * LRn, 0);

    k_alpha_stats<<<MC / 8, 256>>>();
    k_beta_part<<<dim3(LRn / 128, NCH, Bn), 128>>>();
    k_beta_merge<<<MR / 256, 256>>>();
    k_transpose<<<dim3(16, 64, Bn), dim3(32, 8)>>>(gE, gET, LCn, LRn);

    // cd = softmax_r(E) * rs       (A = E rows + exp, B = rs^T)
    k_gemm<1><<<dim3(16, 4, Bn), 256>>>(
        gE, grsT, nullptr, nullptr, gam, gas, nullptr, gcd,
        LRn, LRn, LRn, Dn,
        (size_t)LCn * LRn, (size_t)Dn * LRn, (size_t)LCn * Dn, LCn);

    // rd = softmax_c(E)^T * cs     (A = E^T rows + exp, B = cs^T)
    k_gemm<1><<<dim3(4, 4, Bn), 256>>>(
        gET, gcsT, nullptr, nullptr, gbm, gbs, nullptr, grd,
        LCn, LCn, LCn, Dn,
        (size_t)LRn * LCn, (size_t)Dn * LCn, (size_t)LRn * Dn, LRn);

    // cl = relu([cs|cd|cs*cd] * W1c^T + b1)
    k_gemm<2><<<dim3(MC / 128, 2, 1), 256>>>(
        nullptr, gw1, cs, gcd, nullptr, nullptr, b1, cl,
        3 * Dn, 0, 3 * Dn, Hn, 0, 0, 0, 0);

    // rl = relu([rs|rd|rs*rd] * W2c^T + b2)
    k_gemm<2><<<dim3(MR / 128, 2, 1), 256>>>(
        nullptr, gw2, rs, grd, nullptr, nullptr, b2, rl,
        3 * Dn, 0, 3 * Dn, Hn, 0, 0, 0, 0);
}

// round 7
// speedup vs baseline: 1.3600x; 1.1993x over previous
#include <cuda_runtime.h>
#include <cuda_bf16.h>
#include <math.h>
#include <stdint.h>

#define Bn  32
#define LCn 2048
#define LRn 512
#define Dn  256
#define Hn  128
#define MC  (Bn * LCn)
#define MR  (Bn * LRn)
#define NCH 8

// -------- scratch --------
static __device__ float g_E [(size_t)Bn * LCn * LRn];
static __device__ float g_ET[(size_t)Bn * LRn * LCn];
static __device__ float g_cd[(size_t)Bn * LCn * Dn];
static __device__ float g_rd[(size_t)Bn * LRn * Dn];
static __device__ float g_rsT[(size_t)Bn * Dn * LRn];
static __device__ float g_csT[(size_t)Bn * Dn * LCn];
static __device__ float g_amax[MC], g_asum[MC];
static __device__ float g_bmax[MR], g_bsum[MR];
static __device__ float g_pmax[Bn * NCH * LRn], g_psum[Bn * NCH * LRn];
static __device__ float g_W1c[Hn * 3 * Dn], g_W2c[Hn * 3 * Dn];

// ======================== helpers =============================
__device__ __forceinline__ uint32_t smem_u32(const void* p) {
    uint32_t a;
    asm("{ .reg .u64 t; cvta.to.shared.u64 t, %1; cvt.u32.u64 %0, t; }" : "=r"(a) : "l"(p));
    return a;
}

#define LDSM4(r, addr) \
    asm volatile("ldmatrix.sync.aligned.m8n8.x4.shared.b16 {%0,%1,%2,%3}, [%4];" \
        : "=r"((r)[0]), "=r"((r)[1]), "=r"((r)[2]), "=r"((r)[3]) : "r"(addr))

#define MMA_BF16(c, a, b0, b1) \
    asm volatile("mma.sync.aligned.m16n8k16.row.col.f32.bf16.bf16.f32 " \
        "{%0,%1,%2,%3}, {%4,%5,%6,%7}, {%8,%9}, {%0,%1,%2,%3};" \
        : "+f"((c)[0]), "+f"((c)[1]), "+f"((c)[2]), "+f"((c)[3]) \
        : "r"((a)[0]), "r"((a)[1]), "r"((a)[2]), "r"((a)[3]), "r"(b0), "r"(b1))

#define STS64(addr, v0, v1) \
    asm volatile("st.shared.v2.b32 [%0], {%1,%2};" :: "r"(addr), "r"(v0), "r"(v1) : "memory")

__device__ __forceinline__ void bsplit(float v, uint16_t& h, uint16_t& l) {
    __nv_bfloat16 hb = __float2bfloat16(v);
    h = __bfloat16_as_ushort(hb);
    l = __bfloat16_as_ushort(__float2bfloat16(v - __bfloat162float(hb)));
}

// smem tile layout: [rows][32 k] bf16, row = 64B = 4x16B units.
// Swizzle: quadrant key = (row>>1)&3 so the 4 even rows (banks 0-15) and the
// 4 odd rows (banks 16-31) of any 8-row ldmatrix read land in distinct 16B
// quadrants -> conflict-free LDSM. (Old key (row&3) gave 2-way conflicts.)
__device__ __forceinline__ uint32_t toff(int row, int c16) {
    return (row << 6) + ((c16 ^ ((row >> 1) & 3)) << 4);
}

// A tile 128x32 bf16 = 8192 B (x2 for H/L); B tile 64x32 bf16 = 4096 B (x2)
#define SM_AH 0
#define SM_AL 8192
#define SM_BH 16384
#define SM_BL 20480
#define SMEM_SZ 24576

// ============================================================================
// Unified NT tensor-core GEMM: C[128,64] = A[128,K] * B[64,K]^T (bf16x3)
// MODE 0: plain.  MODE 1: A=exp(A-rmax[row]); epi *= 1/rsum[row].
// MODE 2: A = [X | Y | X*Y] (K=3*Dn); epi = relu(+bias).
// 128x64 CTA tile, 8 warps (4m x 2n), 2 CTAs/SM.
// ============================================================================
template<int MODE>
__global__ void __launch_bounds__(256, 2) k_gemm(
    const float* __restrict__ Ap, const float* __restrict__ Bp,
    const float* __restrict__ Xp, const float* __restrict__ Yp,
    const float* __restrict__ rmax, const float* __restrict__ rsum,
    const float* __restrict__ bias, float* __restrict__ Cp,
    int K, int lda, int ldb, int ldc,
    size_t aB, size_t bB, size_t cB, int sB)
{
    __shared__ __align__(16) uint8_t sm[SMEM_SZ];
    const uint32_t sb = smem_u32(sm);
    const int tid = threadIdx.x;
    const int z = blockIdx.z;
    const int m0 = blockIdx.x * 128, n0 = blockIdx.y * 64;
    const float* A  = Ap + (size_t)z * aB;
    const float* Bm = Bp + (size_t)z * bB;
    float* C = Cp + (size_t)z * cB;

    const int lane = tid & 31, wid = tid >> 5;
    const int wm = wid & 3, wn = wid >> 2;        // 4x2 warps: 32 rows x 32 cols
    const int gid = lane >> 2, tig = lane & 3;
    const int frow = tid >> 3, fk4 = tid & 7;     // A fill: 128 rows x 8 k4
    const int brow = tid >> 3, bk4 = tid & 7;     // B fill rows 0..63 via i<2

    float acc[2][4][4];
    #pragma unroll
    for (int a = 0; a < 2; a++)
        #pragma unroll
        for (int b = 0; b < 4; b++)
            #pragma unroll
            for (int c = 0; c < 4; c++) acc[a][b][c] = 0.f;

    const int S = K >> 5;
    float4 pa[4], pb[2];

    // ---- prefetch chunk 0 ----
    #pragma unroll
    for (int i = 0; i < 4; i++) {
        int row = frow + i * 32;
        if (MODE == 2)
            pa[i] = *(const float4*)(Xp + (size_t)(m0 + row) * Dn + (fk4 << 2));
        else
            pa[i] = *(const float4*)(A + (size_t)(m0 + row) * lda + (fk4 << 2));
    }
    #pragma unroll
    for (int i = 0; i < 2; i++) {
        int row = brow + i * 32;
        if (row < 64)
            pb[i] = *(const float4*)(Bm + (size_t)(n0 + row) * ldb + (bk4 << 2));
    }

    for (int s = 0; s < S; s++) {
        const int k0 = s << 5;
        // ---- convert + STS ----
        #pragma unroll
        for (int i = 0; i < 4; i++) {
            int row = frow + i * 32;
            float4 v = pa[i];
            if (MODE == 1) {
                float rm = __ldg(rmax + (size_t)z * sB + m0 + row);
                v.x = __expf(v.x - rm); v.y = __expf(v.y - rm);
                v.z = __expf(v.z - rm); v.w = __expf(v.w - rm);
            }
            uint16_t h0,h1,h2,h3,l0,l1,l2,l3;
            bsplit(v.x,h0,l0); bsplit(v.y,h1,l1); bsplit(v.z,h2,l2); bsplit(v.w,h3,l3);
            uint32_t off = toff(row, fk4 >> 1) + ((fk4 & 1) << 3);
            STS64(sb + SM_AH + off, (uint32_t)h0 | ((uint32_t)h1 << 16),
                                    (uint32_t)h2 | ((uint32_t)h3 << 16));
            STS64(sb + SM_AL + off, (uint32_t)l0 | ((uint32_t)l1 << 16),
                                    (uint32_t)l2 | ((uint32_t)l3 << 16));
        }
        #pragma unroll
        for (int i = 0; i < 2; i++) {
            int row = brow + i * 32;
            if (row < 64) {
                float4 w = pb[i];
                uint16_t h0,h1,h2,h3,l0,l1,l2,l3;
                bsplit(w.x,h0,l0); bsplit(w.y,h1,l1); bsplit(w.z,h2,l2); bsplit(w.w,h3,l3);
                uint32_t off = toff(row, bk4 >> 1) + ((bk4 & 1) << 3);
                STS64(sb + SM_BH + off, (uint32_t)h0 | ((uint32_t)h1 << 16),
                                        (uint32_t)h2 | ((uint32_t)h3 << 16));
                STS64(sb + SM_BL + off, (uint32_t)l0 | ((uint32_t)l1 << 16),
                                        (uint32_t)l2 | ((uint32_t)l3 << 16));
            }
        }
        __syncthreads();

        // ---- prefetch next chunk ----
        if (s + 1 < S) {
            const int kn = k0 + 32;
            #pragma unroll
            for (int i = 0; i < 4; i++) {
                int row = frow + i * 32;
                if (MODE == 2) {
                    int seg = kn >> 8;
                    int d = (kn & 255) + (fk4 << 2);
                    float4 x = *(const float4*)(Xp + (size_t)(m0 + row) * Dn + d);
                    if (seg == 0) pa[i] = x;
                    else {
                        float4 y = *(const float4*)(Yp + (size_t)(m0 + row) * Dn + d);
                        if (seg == 1) pa[i] = y;
                        else pa[i] = make_float4(x.x*y.x, x.y*y.y, x.z*y.z, x.w*y.w);
                    }
                } else {
                    pa[i] = *(const float4*)(A + (size_t)(m0 + row) * lda + kn + (fk4 << 2));
                }
            }
            #pragma unroll
            for (int i = 0; i < 2; i++) {
                int row = brow + i * 32;
                if (row < 64)
                    pb[i] = *(const float4*)(Bm + (size_t)(n0 + row) * ldb + kn + (bk4 << 2));
            }
        }

        // ---- compute 2 x k16 steps ----
        #pragma unroll
        for (int kb = 0; kb < 2; kb++) {
            uint32_t ah[2][4], al[2][4];
            #pragma unroll
            for (int mb = 0; mb < 2; mb++) {
                int row = wm * 32 + mb * 16 + (lane & 15);
                uint32_t off = toff(row, kb * 2 + (lane >> 4));
                LDSM4(ah[mb], sb + SM_AH + off);
                LDSM4(al[mb], sb + SM_AL + off);
            }
            uint32_t bh[2][4], bl[2][4];
            #pragma unroll
            for (int np = 0; np < 2; np++) {
                int nrow = wn * 32 + np * 16 + (lane & 7) + ((lane >> 4) << 3);
                uint32_t off = toff(nrow, kb * 2 + ((lane >> 3) & 1));
                LDSM4(bh[np], sb + SM_BH + off);
                LDSM4(bl[np], sb + SM_BL + off);
            }
            // HH
            #pragma unroll
            for (int np = 0; np < 2; np++)
                #pragma unroll
                for (int nb = 0; nb < 2; nb++)
                    #pragma unroll
                    for (int mb = 0; mb < 2; mb++)
                        MMA_BF16(acc[mb][np*2+nb], ah[mb], bh[np][nb*2], bh[np][nb*2+1]);
            // HL
            #pragma unroll
            for (int np = 0; np < 2; np++)
                #pragma unroll
                for (int nb = 0; nb < 2; nb++)
                    #pragma unroll
                    for (int mb = 0; mb < 2; mb++)
                        MMA_BF16(acc[mb][np*2+nb], ah[mb], bl[np][nb*2], bl[np][nb*2+1]);
            // LH
            #pragma unroll
            for (int np = 0; np < 2; np++)
                #pragma unroll
                for (int nb = 0; nb < 2; nb++)
                    #pragma unroll
                    for (int mb = 0; mb < 2; mb++)
                        MMA_BF16(acc[mb][np*2+nb], al[mb], bh[np][nb*2], bh[np][nb*2+1]);
        }
        __syncthreads();
    }

    // ---- epilogue ----
    #pragma unroll
    for (int mb = 0; mb < 2; mb++) {
        int r0 = m0 + wm * 32 + mb * 16 + gid;
        int r1 = r0 + 8;
        float s0 = 1.f, s1 = 1.f;
        if (MODE == 1) {
            s0 = 1.0f / rsum[(size_t)z * sB + r0];
            s1 = 1.0f / rsum[(size_t)z * sB + r1];
        }
        #pragma unroll
        for (int nb = 0; nb < 4; nb++) {
            int col = n0 + wn * 32 + nb * 8 + tig * 2;
            float c0 = acc[mb][nb][0], c1 = acc[mb][nb][1];
            float c2 = acc[mb][nb][2], c3 = acc[mb][nb][3];
            if (MODE == 1) { c0 *= s0; c1 *= s0; c2 *= s1; c3 *= s1; }
            if (MODE == 2) {
                float b0v = bias[col], b1v = bias[col + 1];
                c0 = fmaxf(c0 + b0v, 0.f); c1 = fmaxf(c1 + b1v, 0.f);
                c2 = fmaxf(c2 + b0v, 0.f); c3 = fmaxf(c3 + b1v, 0.f);
            }
            *(float2*)(C + (size_t)r0 * ldc + col) = make_float2(c0, c1);
            *(float2*)(C + (size_t)r1 * ldc + col) = make_float2(c2, c3);
        }
    }
}

// ============================================================================
// Batched 32x32 transpose
// ============================================================================
__global__ void k_transpose(const float* __restrict__ src, float* __restrict__ dst,
                            int rows, int cols) {
    __shared__ float t[32][33];
    int b = blockIdx.z;
    src += (size_t)b * rows * cols;
    dst += (size_t)b * rows * cols;
    int c0 = blockIdx.x * 32, r0 = blockIdx.y * 32;
    int x = threadIdx.x, y = threadIdx.y;
    #pragma unroll
    for (int i = 0; i < 32; i += 8)
        t[y + i][x] = src[(size_t)(r0 + y + i) * cols + c0 + x];
    __syncthreads();
    #pragma unroll
    for (int i = 0; i < 32; i += 8)
        dst[(size_t)(c0 + y + i) * rows + r0 + x] = t[x][y + i];
}

// ============================================================================
// Weight folding + softmax stats
// ============================================================================
__global__ void k_wcomb(const float* __restrict__ W1, const float* __restrict__ W2) {
    int i = blockIdx.x * 256 + threadIdx.x;
    if (i >= Hn * Dn) return;
    int h = i >> 8, d = i & (Dn - 1);
    const float* w1 = W1 + (size_t)h * 4 * Dn;
    g_W1c[(size_t)h * 3 * Dn + d]          = w1[d] + w1[2 * Dn + d];
    g_W1c[(size_t)h * 3 * Dn + Dn + d]     = w1[Dn + d] - w1[2 * Dn + d];
    g_W1c[(size_t)h * 3 * Dn + 2 * Dn + d] = w1[3 * Dn + d];
    const float* w2 = W2 + (size_t)h * 4 * Dn;
    g_W2c[(size_t)h * 3 * Dn + d]          = w2[d] + w2[2 * Dn + d];
    g_W2c[(size_t)h * 3 * Dn + Dn + d]     = w2[Dn + d] - w2[2 * Dn + d];
    g_W2c[(size_t)h * 3 * Dn + 2 * Dn + d] = w2[3 * Dn + d];
}

__global__ void k_alpha_stats() {
    int row  = blockIdx.x * 8 + (threadIdx.x >> 5);
    int lane = threadIdx.x & 31;
    const float* e = g_E + (size_t)row * LRn;
    float v[16], m = -1e30f;
    #pragma unroll
    for (int i = 0; i < 16; i++) { v[i] = e[lane + i * 32]; m = fmaxf(m, v[i]); }
    #pragma unroll
    for (int o = 16; o > 0; o >>= 1) m = fmaxf(m, __shfl_xor_sync(0xffffffffu, m, o));
    float s = 0.f;
    #pragma unroll
    for (int i = 0; i < 16; i++) s += __expf(v[i] - m);
    #pragma unroll
    for (int o = 16; o > 0; o >>= 1) s += __shfl_xor_sync(0xffffffffu, s, o);
    if (lane == 0) { g_amax[row] = m; g_asum[row] = s; }
}

__global__ void k_beta_part() {
    int b = blockIdx.z, ch = blockIdx.y;
    int r = blockIdx.x * 128 + threadIdx.x;
    const float* e = g_E + (size_t)b * LCn * LRn + r;
    int c0 = ch * (LCn / NCH);
    float m = -1e30f, s = 0.f;
    for (int c = 0; c < LCn / NCH; c += 4) {
        float v0 = e[(size_t)(c0 + c + 0) * LRn];
        float v1 = e[(size_t)(c0 + c + 1) * LRn];
        float v2 = e[(size_t)(c0 + c + 2) * LRn];
        float v3 = e[(size_t)(c0 + c + 3) * LRn];
        float nm = fmaxf(fmaxf(fmaxf(v0, v1), fmaxf(v2, v3)), m);
        s = s * __expf(m - nm) + __expf(v0 - nm) + __expf(v1 - nm)
                                + __expf(v2 - nm) + __expf(v3 - nm);
        m = nm;
    }
    int idx = (b * NCH + ch) * LRn + r;
    g_pmax[idx] = m; g_psum[idx] = s;
}

__global__ void k_beta_merge() {
    int idx = blockIdx.x * 256 + threadIdx.x;
    int b = idx / LRn, r = idx % LRn;
    float m = -1e30f, s = 0.f;
    #pragma unroll
    for (int ch = 0; ch < NCH; ch++) {
        int p = (b * NCH + ch) * LRn + r;
        float pm = g_pmax[p], ps = g_psum[p];
        float nm = fmaxf(m, pm);
        s = s * __expf(m - nm) + ps * __expf(pm - nm);
        m = nm;
    }
    g_bmax[idx] = m; g_bsum[idx] = s;
}

// ============================================================================
extern "C" void kernel_launch(void* const* d_in, const int* in_sizes, int n_in,
                              void* d_out, int out_size) {
    const float* cs = (const float*)d_in[0];
    const float* rs = (const float*)d_in[1];
    const float* W1 = (const float*)d_in[2];
    const float* b1 = (const float*)d_in[3];
    const float* W2 = (const float*)d_in[4];
    const float* b2 = (const float*)d_in[5];
    float* cl = (float*)d_out;
    float* rl = cl + (size_t)MC * Hn;

    float* gE;  cudaGetSymbolAddress((void**)&gE,  g_E);
    float* gET; cudaGetSymbolAddress((void**)&gET, g_ET);
    float* gcd; cudaGetSymbolAddress((void**)&gcd, g_cd);
    float* grd; cudaGetSymbolAddress((void**)&grd, g_rd);
    float* grsT; cudaGetSymbolAddress((void**)&grsT, g_rsT);
    float* gcsT; cudaGetSymbolAddress((void**)&gcsT, g_csT);
    float* gam; cudaGetSymbolAddress((void**)&gam, g_amax);
    float* gas; cudaGetSymbolAddress((void**)&gas, g_asum);
    float* gbm; cudaGetSymbolAddress((void**)&gbm, g_bmax);
    float* gbs; cudaGetSymbolAddress((void**)&gbs, g_bsum);
    float* gw1; cudaGetSymbolAddress((void**)&gw1, g_W1c);
    float* gw2; cudaGetSymbolAddress((void**)&gw2, g_W2c);

    k_wcomb<<<(Hn * Dn + 255) / 256, 256>>>(W1, W2);
    k_transpose<<<dim3(8, 16, Bn), dim3(32, 8)>>>(rs, grsT, LRn, Dn);
    k_transpose<<<dim3(8, 64, Bn), dim3(32, 8)>>>(cs, gcsT, LCn, Dn);

    // E = cs * rs^T
    k_gemm<0><<<dim3(16, 8, Bn), 256>>>(
        cs, rs, nullptr, nullptr, nullptr, nullptr, nullptr, gE,
        Dn, Dn, Dn, LRn,
        (size_t)LCn * Dn, (size_t)LRn * Dn, (size_t)LCn * LRn, 0);

    k_alpha_stats<<<MC / 8, 256>>>();
    k_beta_part<<<dim3(LRn / 128, NCH, Bn), 128>>>();
    k_beta_merge<<<MR / 256, 256>>>();
    k_transpose<<<dim3(16, 64, Bn), dim3(32, 8)>>>(gE, gET, LCn, LRn);

    // cd = softmax_r(E) * rs       (A = E rows + exp, B = rs^T)
    k_gemm<1><<<dim3(16, 4, Bn), 256>>>(
        gE, grsT, nullptr, nullptr, gam, gas, nullptr, gcd,
        LRn, LRn, LRn, Dn,
        (size_t)LCn * LRn, (size_t)Dn * LRn, (size_t)LCn * Dn, LCn);

    // rd = softmax_c(E)^T * cs     (A = E^T rows + exp, B = cs^T)
    k_gemm<1><<<dim3(4, 4, Bn), 256>>>(
        gET, gcsT, nullptr, nullptr, gbm, gbs, nullptr, grd,
        LCn, LCn, LCn, Dn,
        (size_t)LRn * LCn, (size_t)Dn * LCn, (size_t)LRn * Dn, LRn);

    // cl = relu([cs|cd|cs*cd] * W1c^T + b1)
    k_gemm<2><<<dim3(MC / 128, 2, 1), 256>>>(
        nullptr, gw1, cs, gcd, nullptr, nullptr, b1, cl,
        3 * Dn, 0, 3 * Dn, Hn, 0, 0, 0, 0);

    // rl = relu([rs|rd|rs*rd] * W2c^T + b2)
    k_gemm<2><<<dim3(MR / 128, 2, 1), 256>>>(
        nullptr, gw2, rs, grd, nullptr, nullptr, b2, rl,
        3 * Dn, 0, 3 * Dn, Hn, 0, 0, 0, 0);
}

// round 8
// speedup vs baseline: 1.3921x; 1.0236x over previous
#include <cuda_runtime.h>
#include <cuda_bf16.h>
#include <math.h>
#include <stdint.h>

#define Bn  32
#define LCn 2048
#define LRn 512
#define Dn  256
#define Hn  128
#define MC  (Bn * LCn)
#define MR  (Bn * LRn)
#define NCH 8

typedef __nv_bfloat16 bf16;

// -------- scratch --------
static __device__ float g_E [(size_t)Bn * LCn * LRn];            // fp32 scores
static __device__ bf16 g_EH [(size_t)Bn * LCn * LRn], g_EL [(size_t)Bn * LCn * LRn];
static __device__ bf16 g_ETH[(size_t)Bn * LRn * LCn], g_ETL[(size_t)Bn * LRn * LCn];
static __device__ bf16 g_csH[(size_t)Bn * LCn * Dn],  g_csL[(size_t)Bn * LCn * Dn];
static __device__ bf16 g_rsH[(size_t)Bn * LRn * Dn],  g_rsL[(size_t)Bn * LRn * Dn];
static __device__ bf16 g_csTH[(size_t)Bn * Dn * LCn], g_csTL[(size_t)Bn * Dn * LCn];
static __device__ bf16 g_rsTH[(size_t)Bn * Dn * LRn], g_rsTL[(size_t)Bn * Dn * LRn];
static __device__ bf16 g_cdH[(size_t)Bn * LCn * Dn],  g_cdL[(size_t)Bn * LCn * Dn];
static __device__ bf16 g_pcH[(size_t)Bn * LCn * Dn],  g_pcL[(size_t)Bn * LCn * Dn];
static __device__ bf16 g_rdH[(size_t)Bn * LRn * Dn],  g_rdL[(size_t)Bn * LRn * Dn];
static __device__ bf16 g_prH[(size_t)Bn * LRn * Dn],  g_prL[(size_t)Bn * LRn * Dn];
static __device__ bf16 g_W1H[Hn * 3 * Dn], g_W1L[Hn * 3 * Dn];
static __device__ bf16 g_W2H[Hn * 3 * Dn], g_W2L[Hn * 3 * Dn];
static __device__ float g_amax[MC], g_asum[MC];
static __device__ float g_bmax[MR], g_bsum[MR];
static __device__ float g_pmax[Bn * NCH * LRn], g_psum[Bn * NCH * LRn];

// ======================== helpers =============================
__device__ __forceinline__ uint32_t smem_u32(const void* p) {
    uint32_t a;
    asm("{ .reg .u64 t; cvta.to.shared.u64 t, %1; cvt.u32.u64 %0, t; }" : "=r"(a) : "l"(p));
    return a;
}

#define LDSM4(r, addr) \
    asm volatile("ldmatrix.sync.aligned.m8n8.x4.shared.b16 {%0,%1,%2,%3}, [%4];" \
        : "=r"((r)[0]), "=r"((r)[1]), "=r"((r)[2]), "=r"((r)[3]) : "r"(addr))

#define MMA_BF16(c, a, b0, b1) \
    asm volatile("mma.sync.aligned.m16n8k16.row.col.f32.bf16.bf16.f32 " \
        "{%0,%1,%2,%3}, {%4,%5,%6,%7}, {%8,%9}, {%0,%1,%2,%3};" \
        : "+f"((c)[0]), "+f"((c)[1]), "+f"((c)[2]), "+f"((c)[3]) \
        : "r"((a)[0]), "r"((a)[1]), "r"((a)[2]), "r"((a)[3]), "r"(b0), "r"(b1))

#define CP16(dst, src) \
    asm volatile("cp.async.cg.shared.global [%0], [%1], 16;" :: "r"(dst), "l"(src))
#define CP_COMMIT() asm volatile("cp.async.commit_group;" ::: "memory")
#define CP_WAIT(n)  asm volatile("cp.async.wait_group %0;" :: "n"(n) : "memory")

__device__ __forceinline__ void bsplit(float v, bf16& h, bf16& l) {
    h = __float2bfloat16(v);
    l = __float2bfloat16(v - __bfloat162float(h));
}

// smem tile: [rows][32 k] bf16, row = 64B = 4x16B units; conflict-free swizzle.
__device__ __forceinline__ uint32_t toff16(int row, int u) {
    return (row << 6) + ((u ^ ((row >> 1) & 3)) << 4);
}

// stage: A 128x32 (H,L) + B 64x32 (H,L)
#define SM_AH 0
#define SM_AL 8192
#define SM_BH 16384
#define SM_BL 20480
#define STAGE_B 24576

// ============================================================================
// Unified NT GEMM on pre-split bf16 pairs: C[128,64] = A[128,K]*B[64,K]^T
// (3 products HH+HL+LH).  EPI 0: store fp32.  EPI 1: scale 1/rsum, emit
// split pairs Co=(scaled) and Po=split(X*scaled).  EPI 2: relu(+bias) fp32.
// cp.async double-buffered fill, 128x64 CTA tile, 8 warps, 2 CTAs/SM.
// ============================================================================
template<int EPI>
__global__ void __launch_bounds__(256, 2) k_gemm(
    const bf16* __restrict__ AH0, const bf16* __restrict__ AL0,
    const bf16* __restrict__ AH1, const bf16* __restrict__ AL1,
    const bf16* __restrict__ AH2, const bf16* __restrict__ AL2,
    const bf16* __restrict__ BH,  const bf16* __restrict__ BL,
    const float* __restrict__ rsum, const float* __restrict__ Xf,
    const float* __restrict__ bias, float* __restrict__ Cf,
    bf16* __restrict__ CoH, bf16* __restrict__ CoL,
    bf16* __restrict__ PoH, bf16* __restrict__ PoL,
    int K, int lda, int ldb, int ldc,
    size_t aB, size_t bB, size_t cB, int sB)
{
    __shared__ __align__(16) uint8_t sm[2 * STAGE_B];
    const uint32_t sb = smem_u32(sm);
    const int tid = threadIdx.x;
    const int z = blockIdx.z;
    const int m0 = blockIdx.x * 128, n0 = blockIdx.y * 64;
    const bf16* aH0 = AH0 + (size_t)z * aB;
    const bf16* aL0 = AL0 + (size_t)z * aB;
    const bf16* bH  = BH  + (size_t)z * bB;
    const bf16* bL  = BL  + (size_t)z * bB;

    const int lane = tid & 31, wid = tid >> 5;
    const int wm = wid & 3, wn = wid >> 2;
    const int gid = lane >> 2, tig = lane & 3;

    float acc[2][4][4];
    #pragma unroll
    for (int a = 0; a < 2; a++)
        #pragma unroll
        for (int b = 0; b < 4; b++)
            #pragma unroll
            for (int c = 0; c < 4; c++) acc[a][b][c] = 0.f;

    const int S = K >> 5;

    auto cp_stage = [&](int buf, int kc) {
        const uint32_t tb = sb + buf * STAGE_B;
        const int k0 = kc << 5;
        const bf16* aH = aH0; const bf16* aL = aL0;
        int kk = k0;
        if (EPI == 2) {                    // segment select for FC concat
            int seg = k0 >> 8; kk = k0 & 255;
            if (seg == 1) { aH = AH1; aL = AL1; }
            else if (seg == 2) { aH = AH2; aL = AL2; }
        }
        #pragma unroll
        for (int i = 0; i < 2; i++) {
            int idx = tid + i * 256;
            int row = idx >> 2, u = idx & 3;
            uint32_t off = toff16(row, u);
            const size_t g = (size_t)(m0 + row) * lda + kk + u * 8;
            CP16(tb + SM_AH + off, aH + g);
            CP16(tb + SM_AL + off, aL + g);
        }
        {
            int row = tid >> 2, u = tid & 3;
            uint32_t off = toff16(row, u);
            const size_t g = (size_t)(n0 + row) * ldb + k0 + u * 8;
            CP16(tb + SM_BH + off, bH + g);
            CP16(tb + SM_BL + off, bL + g);
        }
    };

    cp_stage(0, 0);
    CP_COMMIT();

    for (int s = 0; s < S; s++) {
        if (s + 1 < S) {
            cp_stage((s + 1) & 1, s + 1);
            CP_COMMIT();
            CP_WAIT(1);
        } else {
            CP_WAIT(0);
        }
        __syncthreads();

        const uint32_t tb = sb + (s & 1) * STAGE_B;
        #pragma unroll
        for (int kb = 0; kb < 2; kb++) {
            uint32_t ah[2][4], al[2][4];
            #pragma unroll
            for (int mb = 0; mb < 2; mb++) {
                int row = wm * 32 + mb * 16 + (lane & 15);
                uint32_t off = toff16(row, kb * 2 + (lane >> 4));
                LDSM4(ah[mb], tb + SM_AH + off);
                LDSM4(al[mb], tb + SM_AL + off);
            }
            uint32_t bh[2][4], bl[2][4];
            #pragma unroll
            for (int np = 0; np < 2; np++) {
                int nrow = wn * 32 + np * 16 + (lane & 7) + ((lane >> 4) << 3);
                uint32_t off = toff16(nrow, kb * 2 + ((lane >> 3) & 1));
                LDSM4(bh[np], tb + SM_BH + off);
                LDSM4(bl[np], tb + SM_BL + off);
            }
            #pragma unroll
            for (int np = 0; np < 2; np++)
                #pragma unroll
                for (int nb = 0; nb < 2; nb++)
                    #pragma unroll
                    for (int mb = 0; mb < 2; mb++)
                        MMA_BF16(acc[mb][np*2+nb], ah[mb], bh[np][nb*2], bh[np][nb*2+1]);
            #pragma unroll
            for (int np = 0; np < 2; np++)
                #pragma unroll
                for (int nb = 0; nb < 2; nb++)
                    #pragma unroll
                    for (int mb = 0; mb < 2; mb++)
                        MMA_BF16(acc[mb][np*2+nb], ah[mb], bl[np][nb*2], bl[np][nb*2+1]);
            #pragma unroll
            for (int np = 0; np < 2; np++)
                #pragma unroll
                for (int nb = 0; nb < 2; nb++)
                    #pragma unroll
                    for (int mb = 0; mb < 2; mb++)
                        MMA_BF16(acc[mb][np*2+nb], al[mb], bh[np][nb*2], bh[np][nb*2+1]);
        }
        __syncthreads();
    }

    // ---- epilogue ----
    #pragma unroll
    for (int mb = 0; mb < 2; mb++) {
        int r0 = m0 + wm * 32 + mb * 16 + gid;
        int r1 = r0 + 8;
        float s0 = 1.f, s1 = 1.f;
        if (EPI == 1) {
            s0 = 1.0f / rsum[(size_t)z * sB + r0];
            s1 = 1.0f / rsum[(size_t)z * sB + r1];
        }
        #pragma unroll
        for (int nb = 0; nb < 4; nb++) {
            int col = n0 + wn * 32 + nb * 8 + tig * 2;
            float c0 = acc[mb][nb][0], c1 = acc[mb][nb][1];
            float c2 = acc[mb][nb][2], c3 = acc[mb][nb][3];
            if (EPI == 0) {
                float* C = Cf + (size_t)z * cB;
                *(float2*)(C + (size_t)r0 * ldc + col) = make_float2(c0, c1);
                *(float2*)(C + (size_t)r1 * ldc + col) = make_float2(c2, c3);
            } else if (EPI == 2) {
                float b0v = bias[col], b1v = bias[col + 1];
                float* C = Cf;
                *(float2*)(C + (size_t)r0 * ldc + col) =
                    make_float2(fmaxf(c0 + b0v, 0.f), fmaxf(c1 + b1v, 0.f));
                *(float2*)(C + (size_t)r1 * ldc + col) =
                    make_float2(fmaxf(c2 + b0v, 0.f), fmaxf(c3 + b1v, 0.f));
            } else {
                c0 *= s0; c1 *= s0; c2 *= s1; c3 *= s1;
                const float* X = Xf + (size_t)z * cB;
                bf16* cH = CoH + (size_t)z * cB; bf16* cL = CoL + (size_t)z * cB;
                bf16* pH = PoH + (size_t)z * cB; bf16* pL = PoL + (size_t)z * cB;
                size_t o0 = (size_t)r0 * ldc + col, o1 = (size_t)r1 * ldc + col;
                float2 x0 = *(const float2*)(X + o0);
                float2 x1 = *(const float2*)(X + o1);
                bf16 h, l; __nv_bfloat162 hv, lv;
                bsplit(c0, h, l); hv.x = h; lv.x = l;
                bsplit(c1, h, l); hv.y = h; lv.y = l;
                *(__nv_bfloat162*)(cH + o0) = hv; *(__nv_bfloat162*)(cL + o0) = lv;
                bsplit(c2, h, l); hv.x = h; lv.x = l;
                bsplit(c3, h, l); hv.y = h; lv.y = l;
                *(__nv_bfloat162*)(cH + o1) = hv; *(__nv_bfloat162*)(cL + o1) = lv;
                bsplit(x0.x * c0, h, l); hv.x = h; lv.x = l;
                bsplit(x0.y * c1, h, l); hv.y = h; lv.y = l;
                *(__nv_bfloat162*)(pH + o0) = hv; *(__nv_bfloat162*)(pL + o0) = lv;
                bsplit(x1.x * c2, h, l); hv.x = h; lv.x = l;
                bsplit(x1.y * c3, h, l); hv.y = h; lv.y = l;
                *(__nv_bfloat162*)(pH + o1) = hv; *(__nv_bfloat162*)(pL + o1) = lv;
            }
        }
    }
}

// ============================================================================
// Preprocessing passes
// ============================================================================
__global__ void k_split(const float* __restrict__ src, bf16* __restrict__ H,
                        bf16* __restrict__ L) {
    size_t e4 = ((size_t)blockIdx.x * 256 + threadIdx.x) * 4;
    float4 v = *(const float4*)(src + e4);
    bf16 h, l; __nv_bfloat162 h01, h23, l01, l23;
    bsplit(v.x, h, l); h01.x = h; l01.x = l;
    bsplit(v.y, h, l); h01.y = h; l01.y = l;
    bsplit(v.z, h, l); h23.x = h; l23.x = l;
    bsplit(v.w, h, l); h23.y = h; l23.y = l;
    *(__nv_bfloat162*)(H + e4) = h01; *(__nv_bfloat162*)(H + e4 + 2) = h23;
    *(__nv_bfloat162*)(L + e4) = l01; *(__nv_bfloat162*)(L + e4 + 2) = l23;
}

// EH/EL[b,c,r] = split(exp(E - amax[b,c]))
__global__ void k_expsplit(const float* __restrict__ E, const float* __restrict__ amax,
                           bf16* __restrict__ H, bf16* __restrict__ L) {
    size_t e4 = ((size_t)blockIdx.x * 256 + threadIdx.x) * 4;
    size_t row = e4 >> 9;                       // LRn = 512
    float m = __ldg(amax + row);
    float4 v = *(const float4*)(E + e4);
    v.x = __expf(v.x - m); v.y = __expf(v.y - m);
    v.z = __expf(v.z - m); v.w = __expf(v.w - m);
    bf16 h, l; __nv_bfloat162 h01, h23, l01, l23;
    bsplit(v.x, h, l); h01.x = h; l01.x = l;
    bsplit(v.y, h, l); h01.y = h; l01.y = l;
    bsplit(v.z, h, l); h23.x = h; l23.x = l;
    bsplit(v.w, h, l); h23.y = h; l23.y = l;
    *(__nv_bfloat162*)(H + e4) = h01; *(__nv_bfloat162*)(H + e4 + 2) = h23;
    *(__nv_bfloat162*)(L + e4) = l01; *(__nv_bfloat162*)(L + e4 + 2) = l23;
}

// ETH/ETL[b,r,c] = split(exp(E[b,c,r] - bmax[b,r]))   (transpose)
__global__ void k_expsplitT(const float* __restrict__ E, const float* __restrict__ bmax,
                            bf16* __restrict__ H, bf16* __restrict__ L) {
    __shared__ float t[32][33];
    int b = blockIdx.z;
    const float* src = E + (size_t)b * LCn * LRn;
    int r0 = blockIdx.x * 32, c0 = blockIdx.y * 32;
    int x = threadIdx.x, y = threadIdx.y;
    #pragma unroll
    for (int i = 0; i < 32; i += 8)
        t[y + i][x] = src[(size_t)(c0 + y + i) * LRn + r0 + x];
    __syncthreads();
    #pragma unroll
    for (int i = 0; i < 32; i += 8) {
        int r = r0 + y + i;
        float m = bmax[b * LRn + r];
        float v = __expf(t[x][y + i] - m);
        bf16 h, l; bsplit(v, h, l);
        size_t o = (size_t)b * LRn * LCn + (size_t)r * LCn + c0 + x;
        H[o] = h; L[o] = l;
    }
}

// dstH/L[b,c,r] = split(src[b,r,c])   (transpose-split)
__global__ void k_tsplit(const float* __restrict__ src, bf16* __restrict__ H,
                         bf16* __restrict__ L, int rows, int cols) {
    __shared__ float t[32][33];
    int b = blockIdx.z;
    const float* s = src + (size_t)b * rows * cols;
    int c0 = blockIdx.x * 32, r0 = blockIdx.y * 32;
    int x = threadIdx.x, y = threadIdx.y;
    #pragma unroll
    for (int i = 0; i < 32; i += 8)
        t[y + i][x] = s[(size_t)(r0 + y + i) * cols + c0 + x];
    __syncthreads();
    #pragma unroll
    for (int i = 0; i < 32; i += 8) {
        float v = t[x][y + i];
        bf16 h, l; bsplit(v, h, l);
        size_t o = (size_t)b * rows * cols + (size_t)(c0 + y + i) * rows + r0 + x;
        H[o] = h; L[o] = l;
    }
}

__global__ void k_wcomb_split(const float* __restrict__ W1, const float* __restrict__ W2) {
    int i = blockIdx.x * 256 + threadIdx.x;
    if (i >= Hn * Dn) return;
    int hh = i >> 8, d = i & (Dn - 1);
    const float* w1 = W1 + (size_t)hh * 4 * Dn;
    const float* w2 = W2 + (size_t)hh * 4 * Dn;
    float v; bf16 h, l;
    size_t base = (size_t)hh * 3 * Dn + d;
    v = w1[d] + w1[2 * Dn + d];      bsplit(v, h, l); g_W1H[base] = h;          g_W1L[base] = l;
    v = w1[Dn + d] - w1[2 * Dn + d]; bsplit(v, h, l); g_W1H[base + Dn] = h;     g_W1L[base + Dn] = l;
    v = w1[3 * Dn + d];              bsplit(v, h, l); g_W1H[base + 2 * Dn] = h; g_W1L[base + 2 * Dn] = l;
    v = w2[d] + w2[2 * Dn + d];      bsplit(v, h, l); g_W2H[base] = h;          g_W2L[base] = l;
    v = w2[Dn + d] - w2[2 * Dn + d]; bsplit(v, h, l); g_W2H[base + Dn] = h;     g_W2L[base + Dn] = l;
    v = w2[3 * Dn + d];              bsplit(v, h, l); g_W2H[base + 2 * Dn] = h; g_W2L[base + 2 * Dn] = l;
}

// ============================================================================
// Softmax stats (unchanged)
// ============================================================================
__global__ void k_alpha_stats() {
    int row  = blockIdx.x * 8 + (threadIdx.x >> 5);
    int lane = threadIdx.x & 31;
    const float* e = g_E + (size_t)row * LRn;
    float v[16], m = -1e30f;
    #pragma unroll
    for (int i = 0; i < 16; i++) { v[i] = e[lane + i * 32]; m = fmaxf(m, v[i]); }
    #pragma unroll
    for (int o = 16; o > 0; o >>= 1) m = fmaxf(m, __shfl_xor_sync(0xffffffffu, m, o));
    float s = 0.f;
    #pragma unroll
    for (int i = 0; i < 16; i++) s += __expf(v[i] - m);
    #pragma unroll
    for (int o = 16; o > 0; o >>= 1) s += __shfl_xor_sync(0xffffffffu, s, o);
    if (lane == 0) { g_amax[row] = m; g_asum[row] = s; }
}

__global__ void k_beta_part() {
    int b = blockIdx.z, ch = blockIdx.y;
    int r = blockIdx.x * 128 + threadIdx.x;
    const float* e = g_E + (size_t)b * LCn * LRn + r;
    int c0 = ch * (LCn / NCH);
    float m = -1e30f, s = 0.f;
    for (int c = 0; c < LCn / NCH; c += 4) {
        float v0 = e[(size_t)(c0 + c + 0) * LRn];
        float v1 = e[(size_t)(c0 + c + 1) * LRn];
        float v2 = e[(size_t)(c0 + c + 2) * LRn];
        float v3 = e[(size_t)(c0 + c + 3) * LRn];
        float nm = fmaxf(fmaxf(fmaxf(v0, v1), fmaxf(v2, v3)), m);
        s = s * __expf(m - nm) + __expf(v0 - nm) + __expf(v1 - nm)
                                + __expf(v2 - nm) + __expf(v3 - nm);
        m = nm;
    }
    int idx = (b * NCH + ch) * LRn + r;
    g_pmax[idx] = m; g_psum[idx] = s;
}

__global__ void k_beta_merge() {
    int idx = blockIdx.x * 256 + threadIdx.x;
    int b = idx / LRn, r = idx % LRn;
    float m = -1e30f, s = 0.f;
    #pragma unroll
    for (int ch = 0; ch < NCH; ch++) {
        int p = (b * NCH + ch) * LRn + r;
        float pm = g_pmax[p], ps = g_psum[p];
        float nm = fmaxf(m, pm);
        s = s * __expf(m - nm) + ps * __expf(pm - nm);
        m = nm;
    }
    g_bmax[idx] = m; g_bsum[idx] = s;
}

// ============================================================================
extern "C" void kernel_launch(void* const* d_in, const int* in_sizes, int n_in,
                              void* d_out, int out_size) {
    const float* cs = (const float*)d_in[0];
    const float* rs = (const float*)d_in[1];
    const float* W1 = (const float*)d_in[2];
    const float* b1 = (const float*)d_in[3];
    const float* W2 = (const float*)d_in[4];
    const float* b2 = (const float*)d_in[5];
    float* cl = (float*)d_out;
    float* rl = cl + (size_t)MC * Hn;

    float* gE;  cudaGetSymbolAddress((void**)&gE,  g_E);
    bf16 *eH, *eL, *etH, *etL, *csH, *csL, *rsH, *rsL, *ctH, *ctL, *rtH, *rtL;
    bf16 *cdH, *cdL, *pcH, *pcL, *rdH, *rdL, *prH, *prL, *w1H, *w1L, *w2H, *w2L;
    cudaGetSymbolAddress((void**)&eH, g_EH);   cudaGetSymbolAddress((void**)&eL, g_EL);
    cudaGetSymbolAddress((void**)&etH, g_ETH); cudaGetSymbolAddress((void**)&etL, g_ETL);
    cudaGetSymbolAddress((void**)&csH, g_csH); cudaGetSymbolAddress((void**)&csL, g_csL);
    cudaGetSymbolAddress((void**)&rsH, g_rsH); cudaGetSymbolAddress((void**)&rsL, g_rsL);
    cudaGetSymbolAddress((void**)&ctH, g_csTH); cudaGetSymbolAddress((void**)&ctL, g_csTL);
    cudaGetSymbolAddress((void**)&rtH, g_rsTH); cudaGetSymbolAddress((void**)&rtL, g_rsTL);
    cudaGetSymbolAddress((void**)&cdH, g_cdH); cudaGetSymbolAddress((void**)&cdL, g_cdL);
    cudaGetSymbolAddress((void**)&pcH, g_pcH); cudaGetSymbolAddress((void**)&pcL, g_pcL);
    cudaGetSymbolAddress((void**)&rdH, g_rdH); cudaGetSymbolAddress((void**)&rdL, g_rdL);
    cudaGetSymbolAddress((void**)&prH, g_prH); cudaGetSymbolAddress((void**)&prL, g_prL);
    cudaGetSymbolAddress((void**)&w1H, g_W1H); cudaGetSymbolAddress((void**)&w1L, g_W1L);
    cudaGetSymbolAddress((void**)&w2H, g_W2H); cudaGetSymbolAddress((void**)&w2L, g_W2L);
    float *gam, *gas, *gbm, *gbs;
    cudaGetSymbolAddress((void**)&gam, g_amax); cudaGetSymbolAddress((void**)&gas, g_asum);
    cudaGetSymbolAddress((void**)&gbm, g_bmax); cudaGetSymbolAddress((void**)&gbs, g_bsum);

    k_wcomb_split<<<(Hn * Dn + 255) / 256, 256>>>(W1, W2);
    k_split<<<(int)((size_t)MC * Dn / 1024), 256>>>(cs, csH, csL);
    k_split<<<(int)((size_t)MR * Dn / 1024), 256>>>(rs, rsH, rsL);
    k_tsplit<<<dim3(8, 16, Bn), dim3(32, 8)>>>(rs, rtH, rtL, LRn, Dn);
    k_tsplit<<<dim3(8, 64, Bn), dim3(32, 8)>>>(cs, ctH, ctL, LCn, Dn);

    // E = cs * rs^T   (fp32 out)
    k_gemm<0><<<dim3(16, 8, Bn), 256>>>(
        csH, csL, csH, csL, csH, csL, rsH, rsL,
        nullptr, nullptr, nullptr, gE, nullptr, nullptr, nullptr, nullptr,
        Dn, Dn, Dn, LRn,
        (size_t)LCn * Dn, (size_t)LRn * Dn, (size_t)LCn * LRn, 0);

    k_alpha_stats<<<MC / 8, 256>>>();
    k_beta_part<<<dim3(LRn / 128, NCH, Bn), 128>>>();
    k_beta_merge<<<MR / 256, 256>>>();
    k_expsplit<<<(int)((size_t)Bn * LCn * LRn / 1024), 256>>>(gE, gam, eH, eL);
    k_expsplitT<<<dim3(16, 64, Bn), dim3(32, 8)>>>(gE, gbm, etH, etL);

    // cd(+pairs+prod): A = exp-split E (K=512), B = rsT pair
    k_gemm<1><<<dim3(16, 4, Bn), 256>>>(
        eH, eL, eH, eL, eH, eL, rtH, rtL,
        gas, cs, nullptr, nullptr, cdH, cdL, pcH, pcL,
        LRn, LRn, LRn, Dn,
        (size_t)LCn * LRn, (size_t)Dn * LRn, (size_t)LCn * Dn, LCn);

    // rd(+pairs+prod): A = exp-split E^T (K=2048), B = csT pair
    k_gemm<1><<<dim3(4, 4, Bn), 256>>>(
        etH, etL, etH, etL, etH, etL, ctH, ctL,
        gbs, rs, nullptr, nullptr, rdH, rdL, prH, prL,
        LCn, LCn, LCn, Dn,
        (size_t)LRn * LCn, (size_t)Dn * LCn, (size_t)LRn * Dn, LRn);

    // cl = relu([cs|cd|cs*cd] * W1c^T + b1)
    k_gemm<2><<<dim3(MC / 128, 2, 1), 256>>>(
        csH, csL, cdH, cdL, pcH, pcL, w1H, w1L,
        nullptr, nullptr, b1, cl, nullptr, nullptr, nullptr, nullptr,
        3 * Dn, Dn, 3 * Dn, Hn, 0, 0, 0, 0);

    // rl = relu([rs|rd|rs*rd] * W2c^T + b2)
    k_gemm<2><<<dim3(MR / 128, 2, 1), 256>>>(
        rsH, rsL, rdH, rdL, prH, prL, w2H, w2L,
        nullptr, nullptr, b2, rl, nullptr, nullptr, nullptr, nullptr,
        3 * Dn, Dn, 3 * Dn, Hn, 0, 0, 0, 0);
}

// round 9
// speedup vs baseline: 1.4805x; 1.0636x over previous
#include <cuda_runtime.h>
#include <cuda_bf16.h>
#include <math.h>
#include <stdint.h>

#define Bn  32
#define LCn 2048
#define LRn 512
#define Dn  256
#define Hn  128
#define MC  (Bn * LCn)
#define MR  (Bn * LRn)

typedef __nv_bfloat16 bf16;

// -------- scratch --------
static __device__ float g_E [(size_t)Bn * LCn * LRn];            // fp32 scores
static __device__ bf16 g_EH [(size_t)Bn * LCn * LRn], g_EL [(size_t)Bn * LCn * LRn];
static __device__ bf16 g_ETH[(size_t)Bn * LRn * LCn], g_ETL[(size_t)Bn * LRn * LCn];
static __device__ bf16 g_csH[(size_t)Bn * LCn * Dn],  g_csL[(size_t)Bn * LCn * Dn];
static __device__ bf16 g_rsH[(size_t)Bn * LRn * Dn],  g_rsL[(size_t)Bn * LRn * Dn];
static __device__ bf16 g_csTH[(size_t)Bn * Dn * LCn], g_csTL[(size_t)Bn * Dn * LCn];
static __device__ bf16 g_rsTH[(size_t)Bn * Dn * LRn], g_rsTL[(size_t)Bn * Dn * LRn];
static __device__ bf16 g_cdH[(size_t)Bn * LCn * Dn],  g_cdL[(size_t)Bn * LCn * Dn];
static __device__ bf16 g_pcH[(size_t)Bn * LCn * Dn],  g_pcL[(size_t)Bn * LCn * Dn];
static __device__ bf16 g_rdH[(size_t)Bn * LRn * Dn],  g_rdL[(size_t)Bn * LRn * Dn];
static __device__ bf16 g_prH[(size_t)Bn * LRn * Dn],  g_prL[(size_t)Bn * LRn * Dn];
static __device__ bf16 g_W1H[Hn * 3 * Dn], g_W1L[Hn * 3 * Dn];
static __device__ bf16 g_W2H[Hn * 3 * Dn], g_W2L[Hn * 3 * Dn];
static __device__ float g_amax[MC], g_asum[MC];
static __device__ float g_bmax[MR], g_bsum[MR];
// softmax partials from GEMM0 epilogue: rows per 8 n-blocks, cols per 16 m-blocks
static __device__ float g_prM[(size_t)Bn * 8 * LCn], g_prS[(size_t)Bn * 8 * LCn];
static __device__ float g_pcM[(size_t)Bn * 16 * LRn], g_pcS[(size_t)Bn * 16 * LRn];

// ======================== helpers =============================
__device__ __forceinline__ uint32_t smem_u32(const void* p) {
    uint32_t a;
    asm("{ .reg .u64 t; cvta.to.shared.u64 t, %1; cvt.u32.u64 %0, t; }" : "=r"(a) : "l"(p));
    return a;
}

#define LDSM4(r, addr) \
    asm volatile("ldmatrix.sync.aligned.m8n8.x4.shared.b16 {%0,%1,%2,%3}, [%4];" \
        : "=r"((r)[0]), "=r"((r)[1]), "=r"((r)[2]), "=r"((r)[3]) : "r"(addr))

#define MMA_BF16(c, a, b0, b1) \
    asm volatile("mma.sync.aligned.m16n8k16.row.col.f32.bf16.bf16.f32 " \
        "{%0,%1,%2,%3}, {%4,%5,%6,%7}, {%8,%9}, {%0,%1,%2,%3};" \
        : "+f"((c)[0]), "+f"((c)[1]), "+f"((c)[2]), "+f"((c)[3]) \
        : "r"((a)[0]), "r"((a)[1]), "r"((a)[2]), "r"((a)[3]), "r"(b0), "r"(b1))

#define CP16(dst, src) \
    asm volatile("cp.async.cg.shared.global [%0], [%1], 16;" :: "r"(dst), "l"(src))
#define CP_COMMIT() asm volatile("cp.async.commit_group;" ::: "memory")
#define CP_WAIT(n)  asm volatile("cp.async.wait_group %0;" :: "n"(n) : "memory")

__device__ __forceinline__ void bsplit(float v, bf16& h, bf16& l) {
    h = __float2bfloat16(v);
    l = __float2bfloat16(v - __bfloat162float(h));
}

// online (max,sumexp) merge
__device__ __forceinline__ void msmerge(float& m, float& s, float om, float os) {
    float nm = fmaxf(m, om);
    s = s * __expf(m - nm) + os * __expf(om - nm);
    m = nm;
}

// smem tile: [rows][32 k] bf16, row = 64B = 4x16B units; conflict-free swizzle.
__device__ __forceinline__ uint32_t toff16(int row, int u) {
    return (row << 6) + ((u ^ ((row >> 1) & 3)) << 4);
}

// stage: A 128x32 (H,L) + B 64x32 (H,L) = 24 KB
#define SM_AH 0
#define SM_AL 8192
#define SM_BH 16384
#define SM_BL 20480
#define STAGE_B 24576
#define SMEM_DYN (3 * STAGE_B)

// ============================================================================
// Unified NT GEMM on pre-split bf16 pairs: C[128,64] = A[128,K]*B[64,K]^T
// (3 products HH+HL+LH).  EPI 0: fp32 + softmax partial stats.
// EPI 1: scale 1/rsum, emit split pairs + split(X*scaled).  EPI 2: relu+bias.
// 128 threads, 4 warps (32x64 each), 3-stage cp.async, 3 CTAs/SM.
// ============================================================================
template<int EPI>
__global__ void __launch_bounds__(128, 3) k_gemm(
    const bf16* __restrict__ AH0, const bf16* __restrict__ AL0,
    const bf16* __restrict__ AH1, const bf16* __restrict__ AL1,
    const bf16* __restrict__ AH2, const bf16* __restrict__ AL2,
    const bf16* __restrict__ BH,  const bf16* __restrict__ BL,
    const float* __restrict__ rsum, const float* __restrict__ Xf,
    const float* __restrict__ bias, float* __restrict__ Cf,
    bf16* __restrict__ CoH, bf16* __restrict__ CoL,
    bf16* __restrict__ PoH, bf16* __restrict__ PoL,
    float* __restrict__ PrM, float* __restrict__ PrS,
    float* __restrict__ PcM, float* __restrict__ PcS,
    int K, int lda, int ldb, int ldc,
    size_t aB, size_t bB, size_t cB, int sB)
{
    extern __shared__ __align__(16) uint8_t sm[];
    const uint32_t sb = smem_u32(sm);
    const int tid = threadIdx.x;
    const int z = blockIdx.z;
    const int m0 = blockIdx.x * 128, n0 = blockIdx.y * 64;
    const bf16* aH0 = AH0 + (size_t)z * aB;
    const bf16* aL0 = AL0 + (size_t)z * aB;
    const bf16* bH  = BH  + (size_t)z * bB;
    const bf16* bL  = BL  + (size_t)z * bB;

    const int lane = tid & 31, wm = tid >> 5;     // 4 warps stacked in m
    const int gid = lane >> 2, tig = lane & 3;

    float acc[2][8][4];
    #pragma unroll
    for (int a = 0; a < 2; a++)
        #pragma unroll
        for (int b = 0; b < 8; b++)
            #pragma unroll
            for (int c = 0; c < 4; c++) acc[a][b][c] = 0.f;

    const int S = K >> 5;

    auto cp_stage = [&](int buf, int kc) {
        const uint32_t tb = sb + buf * STAGE_B;
        const int k0 = kc << 5;
        const bf16* aH = aH0; const bf16* aL = aL0;
        int kk = k0;
        if (EPI == 2) {
            int seg = k0 >> 8; kk = k0 & 255;
            if (seg == 1) { aH = AH1; aL = AL1; }
            else if (seg == 2) { aH = AH2; aL = AL2; }
        }
        #pragma unroll
        for (int i = 0; i < 4; i++) {
            int idx = tid + i * 128;
            int row = idx >> 2, u = idx & 3;
            uint32_t off = toff16(row, u);
            const size_t g = (size_t)(m0 + row) * lda + kk + u * 8;
            CP16(tb + SM_AH + off, aH + g);
            CP16(tb + SM_AL + off, aL + g);
        }
        #pragma unroll
        for (int i = 0; i < 2; i++) {
            int idx = tid + i * 128;
            int row = idx >> 2, u = idx & 3;
            uint32_t off = toff16(row, u);
            const size_t g = (size_t)(n0 + row) * ldb + k0 + u * 8;
            CP16(tb + SM_BH + off, bH + g);
            CP16(tb + SM_BL + off, bL + g);
        }
    };

    cp_stage(0, 0);
    CP_COMMIT();
    if (S > 1) cp_stage(1, 1);
    CP_COMMIT();

    for (int s = 0; s < S; s++) {
        if (s + 2 < S) cp_stage((s + 2) % 3, s + 2);
        CP_COMMIT();
        CP_WAIT(2);
        __syncthreads();

        const uint32_t tb = sb + (s % 3) * STAGE_B;
        #pragma unroll
        for (int kb = 0; kb < 2; kb++) {
            uint32_t ah[2][4], al[2][4];
            #pragma unroll
            for (int mb = 0; mb < 2; mb++) {
                int row = wm * 32 + mb * 16 + (lane & 15);
                uint32_t off = toff16(row, kb * 2 + (lane >> 4));
                LDSM4(ah[mb], tb + SM_AH + off);
                LDSM4(al[mb], tb + SM_AL + off);
            }
            uint32_t bh[4][4], bl[4][4];
            #pragma unroll
            for (int np = 0; np < 4; np++) {
                int nrow = np * 16 + (lane & 7) + ((lane >> 4) << 3);
                uint32_t off = toff16(nrow, kb * 2 + ((lane >> 3) & 1));
                LDSM4(bh[np], tb + SM_BH + off);
                LDSM4(bl[np], tb + SM_BL + off);
            }
            #pragma unroll
            for (int np = 0; np < 4; np++)
                #pragma unroll
                for (int nb = 0; nb < 2; nb++)
                    #pragma unroll
                    for (int mb = 0; mb < 2; mb++)
                        MMA_BF16(acc[mb][np*2+nb], ah[mb], bh[np][nb*2], bh[np][nb*2+1]);
            #pragma unroll
            for (int np = 0; np < 4; np++)
                #pragma unroll
                for (int nb = 0; nb < 2; nb++)
                    #pragma unroll
                    for (int mb = 0; mb < 2; mb++)
                        MMA_BF16(acc[mb][np*2+nb], ah[mb], bl[np][nb*2], bl[np][nb*2+1]);
            #pragma unroll
            for (int np = 0; np < 4; np++)
                #pragma unroll
                for (int nb = 0; nb < 2; nb++)
                    #pragma unroll
                    for (int mb = 0; mb < 2; mb++)
                        MMA_BF16(acc[mb][np*2+nb], al[mb], bh[np][nb*2], bh[np][nb*2+1]);
        }
        __syncthreads();
    }

    // ---- epilogue ----
    #pragma unroll
    for (int mb = 0; mb < 2; mb++) {
        int r0 = m0 + wm * 32 + mb * 16 + gid;
        int r1 = r0 + 8;
        float s0 = 1.f, s1 = 1.f;
        if (EPI == 1) {
            s0 = 1.0f / rsum[(size_t)z * sB + r0];
            s1 = 1.0f / rsum[(size_t)z * sB + r1];
        }
        #pragma unroll
        for (int nb = 0; nb < 8; nb++) {
            int col = n0 + nb * 8 + tig * 2;
            float c0 = acc[mb][nb][0], c1 = acc[mb][nb][1];
            float c2 = acc[mb][nb][2], c3 = acc[mb][nb][3];
            if (EPI == 0) {
                float* C = Cf + (size_t)z * cB;
                *(float2*)(C + (size_t)r0 * ldc + col) = make_float2(c0, c1);
                *(float2*)(C + (size_t)r1 * ldc + col) = make_float2(c2, c3);
            } else if (EPI == 2) {
                float b0v = bias[col], b1v = bias[col + 1];
                float* C = Cf;
                *(float2*)(C + (size_t)r0 * ldc + col) =
                    make_float2(fmaxf(c0 + b0v, 0.f), fmaxf(c1 + b1v, 0.f));
                *(float2*)(C + (size_t)r1 * ldc + col) =
                    make_float2(fmaxf(c2 + b0v, 0.f), fmaxf(c3 + b1v, 0.f));
            } else {
                c0 *= s0; c1 *= s0; c2 *= s1; c3 *= s1;
                const float* X = Xf + (size_t)z * cB;
                bf16* cH = CoH + (size_t)z * cB; bf16* cL = CoL + (size_t)z * cB;
                bf16* pH = PoH + (size_t)z * cB; bf16* pL = PoL + (size_t)z * cB;
                size_t o0 = (size_t)r0 * ldc + col, o1 = (size_t)r1 * ldc + col;
                float2 x0 = *(const float2*)(X + o0);
                float2 x1 = *(const float2*)(X + o1);
                bf16 h, l; __nv_bfloat162 hv, lv;
                bsplit(c0, h, l); hv.x = h; lv.x = l;
                bsplit(c1, h, l); hv.y = h; lv.y = l;
                *(__nv_bfloat162*)(cH + o0) = hv; *(__nv_bfloat162*)(cL + o0) = lv;
                bsplit(c2, h, l); hv.x = h; lv.x = l;
                bsplit(c3, h, l); hv.y = h; lv.y = l;
                *(__nv_bfloat162*)(cH + o1) = hv; *(__nv_bfloat162*)(cL + o1) = lv;
                bsplit(x0.x * c0, h, l); hv.x = h; lv.x = l;
                bsplit(x0.y * c1, h, l); hv.y = h; lv.y = l;
                *(__nv_bfloat162*)(pH + o0) = hv; *(__nv_bfloat162*)(pL + o0) = lv;
                bsplit(x1.x * c2, h, l); hv.x = h; lv.x = l;
                bsplit(x1.y * c3, h, l); hv.y = h; lv.y = l;
                *(__nv_bfloat162*)(pH + o1) = hv; *(__nv_bfloat162*)(pL + o1) = lv;
            }
        }
    }

    // ---- EPI 0: softmax partial stats from live accumulators ----
    if (EPI == 0) {
        // rows: 4 held rows (mb,half), stats over this CTA's 64 cols
        float rm[4] = {-1e30f, -1e30f, -1e30f, -1e30f};
        float rs[4] = {0.f, 0.f, 0.f, 0.f};
        #pragma unroll
        for (int mb = 0; mb < 2; mb++)
            #pragma unroll
            for (int nb = 0; nb < 8; nb++) {
                rm[mb*2]   = fmaxf(rm[mb*2],   fmaxf(acc[mb][nb][0], acc[mb][nb][1]));
                rm[mb*2+1] = fmaxf(rm[mb*2+1], fmaxf(acc[mb][nb][2], acc[mb][nb][3]));
            }
        #pragma unroll
        for (int mb = 0; mb < 2; mb++)
            #pragma unroll
            for (int nb = 0; nb < 8; nb++) {
                rs[mb*2]   += __expf(acc[mb][nb][0] - rm[mb*2])
                            + __expf(acc[mb][nb][1] - rm[mb*2]);
                rs[mb*2+1] += __expf(acc[mb][nb][2] - rm[mb*2+1])
                            + __expf(acc[mb][nb][3] - rm[mb*2+1]);
            }
        #pragma unroll
        for (int o = 1; o <= 2; o <<= 1)
            #pragma unroll
            for (int j = 0; j < 4; j++) {
                float om = __shfl_xor_sync(0xffffffffu, rm[j], o);
                float os = __shfl_xor_sync(0xffffffffu, rs[j], o);
                msmerge(rm[j], rs[j], om, os);
            }
        if (tig == 0) {
            #pragma unroll
            for (int j = 0; j < 4; j++) {
                int row = m0 + wm * 32 + (j >> 1) * 16 + (j & 1) * 8 + gid;
                size_t o = ((size_t)z * 8 + blockIdx.y) * (size_t)LCn + row;
                PrM[o] = rm[j]; PrS[o] = rs[j];
            }
        }
        // cols: 16 held cols, stats over this CTA's 128 rows
        float cm[16], cs[16];
        #pragma unroll
        for (int q = 0; q < 16; q++) {
            int nb = q >> 1, j2 = q & 1;
            float v0 = acc[0][nb][j2], v1 = acc[0][nb][j2+2];
            float v2 = acc[1][nb][j2], v3 = acc[1][nb][j2+2];
            float m = fmaxf(fmaxf(v0, v1), fmaxf(v2, v3));
            cm[q] = m;
            cs[q] = __expf(v0-m) + __expf(v1-m) + __expf(v2-m) + __expf(v3-m);
        }
        #pragma unroll
        for (int o = 4; o <= 16; o <<= 1)
            #pragma unroll
            for (int q = 0; q < 16; q++) {
                float om = __shfl_xor_sync(0xffffffffu, cm[q], o);
                float os = __shfl_xor_sync(0xffffffffu, cs[q], o);
                msmerge(cm[q], cs[q], om, os);
            }
        float* cw = (float*)sm;             // reuse pipeline smem (2 KB)
        if (gid == 0) {
            #pragma unroll
            for (int q = 0; q < 16; q++) {
                int cl = (q >> 1) * 8 + tig * 2 + (q & 1);
                cw[(wm * 64 + cl) * 2 + 0] = cm[q];
                cw[(wm * 64 + cl) * 2 + 1] = cs[q];
            }
        }
        __syncthreads();
        if (tid < 64) {
            float m = cw[tid * 2], s = cw[tid * 2 + 1];
            #pragma unroll
            for (int w = 1; w < 4; w++)
                msmerge(m, s, cw[(w * 64 + tid) * 2], cw[(w * 64 + tid) * 2 + 1]);
            size_t o = ((size_t)z * 16 + blockIdx.x) * (size_t)LRn + n0 + tid;
            PcM[o] = m; PcS[o] = s;
        }
    }
}

// ============================================================================
// Stat merges
// ============================================================================
__global__ void k_merge_row() {
    int idx = blockIdx.x * 256 + threadIdx.x;          // over MC
    int b = idx >> 11, c = idx & (LCn - 1);
    float m = -1e30f, s = 0.f;
    #pragma unroll
    for (int j = 0; j < 8; j++) {
        size_t o = ((size_t)b * 8 + j) * LCn + c;
        float nm = fmaxf(m, g_prM[o]);
        s = s * __expf(m - nm) + g_prS[o] * __expf(g_prM[o] - nm);
        m = nm;
    }
    g_amax[idx] = m; g_asum[idx] = s;
}

__global__ void k_merge_col() {
    int idx = blockIdx.x * 256 + threadIdx.x;          // over MR
    int b = idx >> 9, r = idx & (LRn - 1);
    float m = -1e30f, s = 0.f;
    #pragma unroll
    for (int j = 0; j < 16; j++) {
        size_t o = ((size_t)b * 16 + j) * LRn + r;
        float nm = fmaxf(m, g_pcM[o]);
        s = s * __expf(m - nm) + g_pcS[o] * __expf(g_pcM[o] - nm);
        m = nm;
    }
    g_bmax[idx] = m; g_bsum[idx] = s;
}

// ============================================================================
// Fused exp pass: one read of E -> EH/EL (row-normalized) + ETH/ETL (col-norm,
// transposed).
// ============================================================================
__global__ void k_expboth() {
    __shared__ float t[32][33];
    int z = blockIdx.z;
    int r0 = blockIdx.x * 32, c0 = blockIdx.y * 32;
    int x = threadIdx.x, y = threadIdx.y;
    const float* src = g_E + (size_t)z * LCn * LRn;
    #pragma unroll
    for (int i = 0; i < 32; i += 8) {
        int c = c0 + y + i;
        float v = src[(size_t)c * LRn + r0 + x];
        t[y + i][x] = v;
        float e = __expf(v - g_amax[z * LCn + c]);
        bf16 h, l; bsplit(e, h, l);
        size_t o = (size_t)z * LCn * LRn + (size_t)c * LRn + r0 + x;
        g_EH[o] = h; g_EL[o] = l;
    }
    __syncthreads();
    #pragma unroll
    for (int i = 0; i < 32; i += 8) {
        int r = r0 + y + i;
        float e = __expf(t[x][y + i] - g_bmax[z * LRn + r]);
        bf16 h, l; bsplit(e, h, l);
        size_t o = (size_t)z * LRn * LCn + (size_t)r * LCn + c0 + x;
        g_ETH[o] = h; g_ETL[o] = l;
    }
}

// ============================================================================
// Preprocessing
// ============================================================================
__global__ void k_split(const float* __restrict__ src, bf16* __restrict__ H,
                        bf16* __restrict__ L) {
    size_t e4 = ((size_t)blockIdx.x * 256 + threadIdx.x) * 4;
    float4 v = *(const float4*)(src + e4);
    bf16 h, l; __nv_bfloat162 h01, h23, l01, l23;
    bsplit(v.x, h, l); h01.x = h; l01.x = l;
    bsplit(v.y, h, l); h01.y = h; l01.y = l;
    bsplit(v.z, h, l); h23.x = h; l23.x = l;
    bsplit(v.w, h, l); h23.y = h; l23.y = l;
    *(__nv_bfloat162*)(H + e4) = h01; *(__nv_bfloat162*)(H + e4 + 2) = h23;
    *(__nv_bfloat162*)(L + e4) = l01; *(__nv_bfloat162*)(L + e4 + 2) = l23;
}

__global__ void k_tsplit(const float* __restrict__ src, bf16* __restrict__ H,
                         bf16* __restrict__ L, int rows, int cols) {
    __shared__ float t[32][33];
    int b = blockIdx.z;
    const float* s = src + (size_t)b * rows * cols;
    int c0 = blockIdx.x * 32, r0 = blockIdx.y * 32;
    int x = threadIdx.x, y = threadIdx.y;
    #pragma unroll
    for (int i = 0; i < 32; i += 8)
        t[y + i][x] = s[(size_t)(r0 + y + i) * cols + c0 + x];
    __syncthreads();
    #pragma unroll
    for (int i = 0; i < 32; i += 8) {
        float v = t[x][y + i];
        bf16 h, l; bsplit(v, h, l);
        size_t o = (size_t)b * rows * cols + (size_t)(c0 + y + i) * rows + r0 + x;
        H[o] = h; L[o] = l;
    }
}

__global__ void k_wcomb_split(const float* __restrict__ W1, const float* __restrict__ W2) {
    int i = blockIdx.x * 256 + threadIdx.x;
    if (i >= Hn * Dn) return;
    int hh = i >> 8, d = i & (Dn - 1);
    const float* w1 = W1 + (size_t)hh * 4 * Dn;
    const float* w2 = W2 + (size_t)hh * 4 * Dn;
    float v; bf16 h, l;
    size_t base = (size_t)hh * 3 * Dn + d;
    v = w1[d] + w1[2 * Dn + d];      bsplit(v, h, l); g_W1H[base] = h;          g_W1L[base] = l;
    v = w1[Dn + d] - w1[2 * Dn + d]; bsplit(v, h, l); g_W1H[base + Dn] = h;     g_W1L[base + Dn] = l;
    v = w1[3 * Dn + d];              bsplit(v, h, l); g_W1H[base + 2 * Dn] = h; g_W1L[base + 2 * Dn] = l;
    v = w2[d] + w2[2 * Dn + d];      bsplit(v, h, l); g_W2H[base] = h;          g_W2L[base] = l;
    v = w2[Dn + d] - w2[2 * Dn + d]; bsplit(v, h, l); g_W2H[base + Dn] = h;     g_W2L[base + Dn] = l;
    v = w2[3 * Dn + d];              bsplit(v, h, l); g_W2H[base + 2 * Dn] = h; g_W2L[base + 2 * Dn] = l;
}

// ============================================================================
extern "C" void kernel_launch(void* const* d_in, const int* in_sizes, int n_in,
                              void* d_out, int out_size) {
    const float* cs = (const float*)d_in[0];
    const float* rs = (const float*)d_in[1];
    const float* W1 = (const float*)d_in[2];
    const float* b1 = (const float*)d_in[3];
    const float* W2 = (const float*)d_in[4];
    const float* b2 = (const float*)d_in[5];
    float* cl = (float*)d_out;
    float* rl = cl + (size_t)MC * Hn;

    float* gE;  cudaGetSymbolAddress((void**)&gE,  g_E);
    bf16 *eH, *eL, *etH, *etL, *csH, *csL, *rsH, *rsL, *ctH, *ctL, *rtH, *rtL;
    bf16 *cdH, *cdL, *pcH, *pcL, *rdH, *rdL, *prH, *prL, *w1H, *w1L, *w2H, *w2L;
    cudaGetSymbolAddress((void**)&eH, g_EH);   cudaGetSymbolAddress((void**)&eL, g_EL);
    cudaGetSymbolAddress((void**)&etH, g_ETH); cudaGetSymbolAddress((void**)&etL, g_ETL);
    cudaGetSymbolAddress((void**)&csH, g_csH); cudaGetSymbolAddress((void**)&csL, g_csL);
    cudaGetSymbolAddress((void**)&rsH, g_rsH); cudaGetSymbolAddress((void**)&rsL, g_rsL);
    cudaGetSymbolAddress((void**)&ctH, g_csTH); cudaGetSymbolAddress((void**)&ctL, g_csTL);
    cudaGetSymbolAddress((void**)&rtH, g_rsTH); cudaGetSymbolAddress((void**)&rtL, g_rsTL);
    cudaGetSymbolAddress((void**)&cdH, g_cdH); cudaGetSymbolAddress((void**)&cdL, g_cdL);
    cudaGetSymbolAddress((void**)&pcH, g_pcH); cudaGetSymbolAddress((void**)&pcL, g_pcL);
    cudaGetSymbolAddress((void**)&rdH, g_rdH); cudaGetSymbolAddress((void**)&rdL, g_rdL);
    cudaGetSymbolAddress((void**)&prH, g_prH); cudaGetSymbolAddress((void**)&prL, g_prL);
    cudaGetSymbolAddress((void**)&w1H, g_W1H); cudaGetSymbolAddress((void**)&w1L, g_W1L);
    cudaGetSymbolAddress((void**)&w2H, g_W2H); cudaGetSymbolAddress((void**)&w2L, g_W2L);
    float *gas, *gbs, *prM, *prS, *pcM, *pcS;
    cudaGetSymbolAddress((void**)&gas, g_asum);
    cudaGetSymbolAddress((void**)&gbs, g_bsum);
    cudaGetSymbolAddress((void**)&prM, g_prM); cudaGetSymbolAddress((void**)&prS, g_prS);
    cudaGetSymbolAddress((void**)&pcM, g_pcM); cudaGetSymbolAddress((void**)&pcS, g_pcS);

    cudaFuncSetAttribute(k_gemm<0>, cudaFuncAttributeMaxDynamicSharedMemorySize, SMEM_DYN);
    cudaFuncSetAttribute(k_gemm<1>, cudaFuncAttributeMaxDynamicSharedMemorySize, SMEM_DYN);
    cudaFuncSetAttribute(k_gemm<2>, cudaFuncAttributeMaxDynamicSharedMemorySize, SMEM_DYN);

    k_wcomb_split<<<(Hn * Dn + 255) / 256, 256>>>(W1, W2);
    k_split<<<(int)((size_t)MC * Dn / 1024), 256>>>(cs, csH, csL);
    k_split<<<(int)((size_t)MR * Dn / 1024), 256>>>(rs, rsH, rsL);
    k_tsplit<<<dim3(8, 16, Bn), dim3(32, 8)>>>(rs, rtH, rtL, LRn, Dn);
    k_tsplit<<<dim3(8, 64, Bn), dim3(32, 8)>>>(cs, ctH, ctL, LCn, Dn);

    // E = cs * rs^T  (fp32 out + softmax partials)
    k_gemm<0><<<dim3(16, 8, Bn), 128, SMEM_DYN>>>(
        csH, csL, csH, csL, csH, csL, rsH, rsL,
        nullptr, nullptr, nullptr, gE, nullptr, nullptr, nullptr, nullptr,
        prM, prS, pcM, pcS,
        Dn, Dn, Dn, LRn,
        (size_t)LCn * Dn, (size_t)LRn * Dn, (size_t)LCn * LRn, 0);

    k_merge_row<<<MC / 256, 256>>>();
    k_merge_col<<<MR / 256, 256>>>();
    k_expboth<<<dim3(16, 64, Bn), dim3(32, 8)>>>();

    // cd(+pairs+prod): A = exp-split E (K=512), B = rsT pair
    k_gemm<1><<<dim3(16, 4, Bn), 128, SMEM_DYN>>>(
        eH, eL, eH, eL, eH, eL, rtH, rtL,
        gas, cs, nullptr, nullptr, cdH, cdL, pcH, pcL,
        nullptr, nullptr, nullptr, nullptr,
        LRn, LRn, LRn, Dn,
        (size_t)LCn * LRn, (size_t)Dn * LRn, (size_t)LCn * Dn, LCn);

    // rd(+pairs+prod): A = exp-split E^T (K=2048), B = csT pair
    k_gemm<1><<<dim3(4, 4, Bn), 128, SMEM_DYN>>>(
        etH, etL, etH, etL, etH, etL, ctH, ctL,
        gbs, rs, nullptr, nullptr, rdH, rdL, prH, prL,
        nullptr, nullptr, nullptr, nullptr,
        LCn, LCn, LCn, Dn,
        (size_t)LRn * LCn, (size_t)Dn * LCn, (size_t)LRn * Dn, LRn);

    // cl = relu([cs|cd|cs*cd] * W1c^T + b1)
    k_gemm<2><<<dim3(MC / 128, 2, 1), 128, SMEM_DYN>>>(
        csH, csL, cdH, cdL, pcH, pcL, w1H, w1L,
        nullptr, nullptr, b1, cl, nullptr, nullptr, nullptr, nullptr,
        nullptr, nullptr, nullptr, nullptr,
        3 * Dn, Dn, 3 * Dn, Hn, 0, 0, 0, 0);

    // rl = relu([rs|rd|rs*rd] * W2c^T + b2)
    k_gemm<2><<<dim3(MR / 128, 2, 1), 128, SMEM_DYN>>>(
        rsH, rsL, rdH, rdL, prH, prL, w2H, w2L,
        nullptr, nullptr, b2, rl, nullptr, nullptr, nullptr, nullptr,
        nullptr, nullptr, nullptr, nullptr,
        3 * Dn, Dn, 3 * Dn, Hn, 0, 0, 0, 0);
}

// round 10
// speedup vs baseline: 1.4825x; 1.0013x over previous
#include <cuda_runtime.h>
#include <cuda_bf16.h>
#include <math.h>
#include <stdint.h>

#define Bn  32
#define LCn 2048
#define LRn 512
#define Dn  256
#define Hn  128
#define MC  (Bn * LCn)
#define MR  (Bn * LRn)

typedef __nv_bfloat16 bf16;

// -------- scratch --------
static __device__ float g_E [(size_t)Bn * LCn * LRn];            // fp32 scores
static __device__ bf16 g_EH [(size_t)Bn * LCn * LRn], g_EL [(size_t)Bn * LCn * LRn];
static __device__ bf16 g_ETH[(size_t)Bn * LRn * LCn], g_ETL[(size_t)Bn * LRn * LCn];
static __device__ bf16 g_csH[(size_t)Bn * LCn * Dn],  g_csL[(size_t)Bn * LCn * Dn];
static __device__ bf16 g_rsH[(size_t)Bn * LRn * Dn],  g_rsL[(size_t)Bn * LRn * Dn];
static __device__ bf16 g_csTH[(size_t)Bn * Dn * LCn], g_csTL[(size_t)Bn * Dn * LCn];
static __device__ bf16 g_rsTH[(size_t)Bn * Dn * LRn], g_rsTL[(size_t)Bn * Dn * LRn];
static __device__ bf16 g_cdH[(size_t)Bn * LCn * Dn],  g_cdL[(size_t)Bn * LCn * Dn];
static __device__ bf16 g_pcH[(size_t)Bn * LCn * Dn],  g_pcL[(size_t)Bn * LCn * Dn];
static __device__ bf16 g_rdH[(size_t)Bn * LRn * Dn],  g_rdL[(size_t)Bn * LRn * Dn];
static __device__ bf16 g_prH[(size_t)Bn * LRn * Dn],  g_prL[(size_t)Bn * LRn * Dn];
static __device__ bf16 g_W1H[Hn * 3 * Dn], g_W1L[Hn * 3 * Dn];
static __device__ bf16 g_W2H[Hn * 3 * Dn], g_W2L[Hn * 3 * Dn];
static __device__ float g_amax[MC], g_asum[MC];
static __device__ float g_bmax[MR], g_bsum[MR];
// softmax partials from GEMM0 epilogue: rows per 8 n-blocks(64), cols per 32 m-blocks(64)
static __device__ float g_prM[(size_t)Bn * 8 * LCn], g_prS[(size_t)Bn * 8 * LCn];
static __device__ float g_pcM[(size_t)Bn * 32 * LRn], g_pcS[(size_t)Bn * 32 * LRn];

// ======================== helpers =============================
__device__ __forceinline__ uint32_t smem_u32(const void* p) {
    uint32_t a;
    asm("{ .reg .u64 t; cvta.to.shared.u64 t, %1; cvt.u32.u64 %0, t; }" : "=r"(a) : "l"(p));
    return a;
}

#define LDSM4(r, addr) \
    asm volatile("ldmatrix.sync.aligned.m8n8.x4.shared.b16 {%0,%1,%2,%3}, [%4];" \
        : "=r"((r)[0]), "=r"((r)[1]), "=r"((r)[2]), "=r"((r)[3]) : "r"(addr))

#define MMA_BF16(c, a, b0, b1) \
    asm volatile("mma.sync.aligned.m16n8k16.row.col.f32.bf16.bf16.f32 " \
        "{%0,%1,%2,%3}, {%4,%5,%6,%7}, {%8,%9}, {%0,%1,%2,%3};" \
        : "+f"((c)[0]), "+f"((c)[1]), "+f"((c)[2]), "+f"((c)[3]) \
        : "r"((a)[0]), "r"((a)[1]), "r"((a)[2]), "r"((a)[3]), "r"(b0), "r"(b1))

#define CP16(dst, src) \
    asm volatile("cp.async.cg.shared.global [%0], [%1], 16;" :: "r"(dst), "l"(src))
#define CP_COMMIT() asm volatile("cp.async.commit_group;" ::: "memory")
#define CP_WAIT(n)  asm volatile("cp.async.wait_group %0;" :: "n"(n) : "memory")

__device__ __forceinline__ void bsplit(float v, bf16& h, bf16& l) {
    h = __float2bfloat16(v);
    l = __float2bfloat16(v - __bfloat162float(h));
}

__device__ __forceinline__ void msmerge(float& m, float& s, float om, float os) {
    float nm = fmaxf(m, om);
    s = s * __expf(m - nm) + os * __expf(om - nm);
    m = nm;
}

// smem tile: [rows][32 k] bf16, row = 64B = 4x16B units; conflict-free swizzle.
__device__ __forceinline__ uint32_t toff16(int row, int u) {
    return (row << 6) + ((u ^ ((row >> 1) & 3)) << 4);
}

// stage: A 128x32 (H,L) + B 128x32 (H,L) = 32 KB
#define SM_AH 0
#define SM_AL 8192
#define SM_BH 16384
#define SM_BL 24576
#define STAGE_B 32768
#define SMEM_DYN (3 * STAGE_B)

// ============================================================================
// Unified NT GEMM on pre-split bf16 pairs: C[128,128] = A[128,K]*B[128,K]^T
// (3 products HH+HL+LH).  EPI 0: fp32 + softmax partial stats.
// EPI 1: scale 1/rsum, emit split pairs + split(X*scaled).  EPI 2: relu+bias.
// 128 threads, 4 warps (2x2, 64x64 each), 3-stage cp.async, 2 CTAs/SM.
// ============================================================================
template<int EPI>
__global__ void __launch_bounds__(128, 2) k_gemm(
    const bf16* __restrict__ AH0, const bf16* __restrict__ AL0,
    const bf16* __restrict__ AH1, const bf16* __restrict__ AL1,
    const bf16* __restrict__ AH2, const bf16* __restrict__ AL2,
    const bf16* __restrict__ BH,  const bf16* __restrict__ BL,
    const float* __restrict__ rsum, const float* __restrict__ Xf,
    const float* __restrict__ bias, float* __restrict__ Cf,
    bf16* __restrict__ CoH, bf16* __restrict__ CoL,
    bf16* __restrict__ PoH, bf16* __restrict__ PoL,
    float* __restrict__ PrM, float* __restrict__ PrS,
    float* __restrict__ PcM, float* __restrict__ PcS,
    int K, int lda, int ldb, int ldc,
    size_t aB, size_t bB, size_t cB, int sB)
{
    extern __shared__ __align__(16) uint8_t sm[];
    const uint32_t sb = smem_u32(sm);
    const int tid = threadIdx.x;
    const int z = blockIdx.z;
    const int m0 = blockIdx.x * 128, n0 = blockIdx.y * 128;
    const bf16* aH0 = AH0 + (size_t)z * aB;
    const bf16* aL0 = AL0 + (size_t)z * aB;
    const bf16* bH  = BH  + (size_t)z * bB;
    const bf16* bL  = BL  + (size_t)z * bB;

    const int lane = tid & 31, wid = tid >> 5;
    const int wm = wid & 1, wn = wid >> 1;        // 2x2 warps, 64x64 each
    const int gid = lane >> 2, tig = lane & 3;

    float acc[4][8][4];
    #pragma unroll
    for (int a = 0; a < 4; a++)
        #pragma unroll
        for (int b = 0; b < 8; b++)
            #pragma unroll
            for (int c = 0; c < 4; c++) acc[a][b][c] = 0.f;

    const int S = K >> 5;

    auto cp_stage = [&](int buf, int kc) {
        const uint32_t tb = sb + buf * STAGE_B;
        const int k0 = kc << 5;
        const bf16* aH = aH0; const bf16* aL = aL0;
        int kk = k0;
        if (EPI == 2) {
            int seg = k0 >> 8; kk = k0 & 255;
            if (seg == 1) { aH = AH1; aL = AL1; }
            else if (seg == 2) { aH = AH2; aL = AL2; }
        }
        #pragma unroll
        for (int i = 0; i < 4; i++) {
            int idx = tid + i * 128;
            int row = idx >> 2, u = idx & 3;
            uint32_t off = toff16(row, u);
            const size_t g = (size_t)(m0 + row) * lda + kk + u * 8;
            CP16(tb + SM_AH + off, aH + g);
            CP16(tb + SM_AL + off, aL + g);
        }
        #pragma unroll
        for (int i = 0; i < 4; i++) {
            int idx = tid + i * 128;
            int row = idx >> 2, u = idx & 3;
            uint32_t off = toff16(row, u);
            const size_t g = (size_t)(n0 + row) * ldb + k0 + u * 8;
            CP16(tb + SM_BH + off, bH + g);
            CP16(tb + SM_BL + off, bL + g);
        }
    };

    cp_stage(0, 0);
    CP_COMMIT();
    if (S > 1) cp_stage(1, 1);
    CP_COMMIT();

    for (int s = 0; s < S; s++) {
        if (s + 2 < S) cp_stage((s + 2) % 3, s + 2);
        CP_COMMIT();
        CP_WAIT(2);
        __syncthreads();

        const uint32_t tb = sb + (s % 3) * STAGE_B;
        #pragma unroll
        for (int kb = 0; kb < 2; kb++) {
            uint32_t ah[4][4], al[4][4];
            #pragma unroll
            for (int mb = 0; mb < 4; mb++) {
                int row = wm * 64 + mb * 16 + (lane & 15);
                uint32_t off = toff16(row, kb * 2 + (lane >> 4));
                LDSM4(ah[mb], tb + SM_AH + off);
                LDSM4(al[mb], tb + SM_AL + off);
            }
            #pragma unroll
            for (int np = 0; np < 4; np++) {
                int nrow = wn * 64 + np * 16 + (lane & 7) + ((lane >> 4) << 3);
                uint32_t off = toff16(nrow, kb * 2 + ((lane >> 3) & 1));
                uint32_t bh[4], bl[4];
                LDSM4(bh, tb + SM_BH + off);
                LDSM4(bl, tb + SM_BL + off);
                // HH
                #pragma unroll
                for (int nb = 0; nb < 2; nb++)
                    #pragma unroll
                    for (int mb = 0; mb < 4; mb++)
                        MMA_BF16(acc[mb][np*2+nb], ah[mb], bh[nb*2], bh[nb*2+1]);
                // HL
                #pragma unroll
                for (int nb = 0; nb < 2; nb++)
                    #pragma unroll
                    for (int mb = 0; mb < 4; mb++)
                        MMA_BF16(acc[mb][np*2+nb], ah[mb], bl[nb*2], bl[nb*2+1]);
                // LH
                #pragma unroll
                for (int nb = 0; nb < 2; nb++)
                    #pragma unroll
                    for (int mb = 0; mb < 4; mb++)
                        MMA_BF16(acc[mb][np*2+nb], al[mb], bh[nb*2], bh[nb*2+1]);
            }
        }
        __syncthreads();
    }

    // ---- epilogue ----
    #pragma unroll
    for (int mb = 0; mb < 4; mb++) {
        int r0 = m0 + wm * 64 + mb * 16 + gid;
        int r1 = r0 + 8;
        float s0 = 1.f, s1 = 1.f;
        if (EPI == 1) {
            s0 = 1.0f / rsum[(size_t)z * sB + r0];
            s1 = 1.0f / rsum[(size_t)z * sB + r1];
        }
        #pragma unroll
        for (int nb = 0; nb < 8; nb++) {
            int col = n0 + wn * 64 + nb * 8 + tig * 2;
            float c0 = acc[mb][nb][0], c1 = acc[mb][nb][1];
            float c2 = acc[mb][nb][2], c3 = acc[mb][nb][3];
            if (EPI == 0) {
                float* C = Cf + (size_t)z * cB;
                *(float2*)(C + (size_t)r0 * ldc + col) = make_float2(c0, c1);
                *(float2*)(C + (size_t)r1 * ldc + col) = make_float2(c2, c3);
            } else if (EPI == 2) {
                float b0v = bias[col], b1v = bias[col + 1];
                float* C = Cf;
                *(float2*)(C + (size_t)r0 * ldc + col) =
                    make_float2(fmaxf(c0 + b0v, 0.f), fmaxf(c1 + b1v, 0.f));
                *(float2*)(C + (size_t)r1 * ldc + col) =
                    make_float2(fmaxf(c2 + b0v, 0.f), fmaxf(c3 + b1v, 0.f));
            } else {
                c0 *= s0; c1 *= s0; c2 *= s1; c3 *= s1;
                const float* X = Xf + (size_t)z * cB;
                bf16* cH = CoH + (size_t)z * cB; bf16* cL = CoL + (size_t)z * cB;
                bf16* pH = PoH + (size_t)z * cB; bf16* pL = PoL + (size_t)z * cB;
                size_t o0 = (size_t)r0 * ldc + col, o1 = (size_t)r1 * ldc + col;
                float2 x0 = *(const float2*)(X + o0);
                float2 x1 = *(const float2*)(X + o1);
                bf16 h, l; __nv_bfloat162 hv, lv;
                bsplit(c0, h, l); hv.x = h; lv.x = l;
                bsplit(c1, h, l); hv.y = h; lv.y = l;
                *(__nv_bfloat162*)(cH + o0) = hv; *(__nv_bfloat162*)(cL + o0) = lv;
                bsplit(c2, h, l); hv.x = h; lv.x = l;
                bsplit(c3, h, l); hv.y = h; lv.y = l;
                *(__nv_bfloat162*)(cH + o1) = hv; *(__nv_bfloat162*)(cL + o1) = lv;
                bsplit(x0.x * c0, h, l); hv.x = h; lv.x = l;
                bsplit(x0.y * c1, h, l); hv.y = h; lv.y = l;
                *(__nv_bfloat162*)(pH + o0) = hv; *(__nv_bfloat162*)(pL + o0) = lv;
                bsplit(x1.x * c2, h, l); hv.x = h; lv.x = l;
                bsplit(x1.y * c3, h, l); hv.y = h; lv.y = l;
                *(__nv_bfloat162*)(pH + o1) = hv; *(__nv_bfloat162*)(pL + o1) = lv;
            }
        }
    }

    // ---- EPI 0: softmax partial stats from live accumulators ----
    if (EPI == 0) {
        // row stats: 8 rows/thread (mb, half) over this warp's 64 cols
        float rm[8], rs[8];
        #pragma unroll
        for (int mb = 0; mb < 4; mb++)
            #pragma unroll
            for (int h = 0; h < 2; h++) {
                float m = -1e30f;
                #pragma unroll
                for (int nb = 0; nb < 8; nb++)
                    m = fmaxf(m, fmaxf(acc[mb][nb][h*2], acc[mb][nb][h*2+1]));
                float ss = 0.f;
                #pragma unroll
                for (int nb = 0; nb < 8; nb++)
                    ss += __expf(acc[mb][nb][h*2] - m) + __expf(acc[mb][nb][h*2+1] - m);
                rm[mb*2+h] = m; rs[mb*2+h] = ss;
            }
        #pragma unroll
        for (int o = 1; o <= 2; o <<= 1)
            #pragma unroll
            for (int j = 0; j < 8; j++) {
                float om = __shfl_xor_sync(0xffffffffu, rm[j], o);
                float os = __shfl_xor_sync(0xffffffffu, rs[j], o);
                msmerge(rm[j], rs[j], om, os);
            }
        if (tig == 0) {
            #pragma unroll
            for (int j = 0; j < 8; j++) {
                int row = m0 + wm * 64 + (j >> 1) * 16 + (j & 1) * 8 + gid;
                size_t o = ((size_t)z * 8 + blockIdx.y * 2 + wn) * (size_t)LCn + row;
                PrM[o] = rm[j]; PrS[o] = rs[j];
            }
        }
        // col stats: 16 cols/thread (nb, j) over this warp's 64 rows
        float cm[16], cs[16];
        #pragma unroll
        for (int nb = 0; nb < 8; nb++)
            #pragma unroll
            for (int j = 0; j < 2; j++) {
                float m = -1e30f;
                #pragma unroll
                for (int mb = 0; mb < 4; mb++)
                    m = fmaxf(m, fmaxf(acc[mb][nb][j], acc[mb][nb][j+2]));
                float ss = 0.f;
                #pragma unroll
                for (int mb = 0; mb < 4; mb++)
                    ss += __expf(acc[mb][nb][j] - m) + __expf(acc[mb][nb][j+2] - m);
                cm[nb*2+j] = m; cs[nb*2+j] = ss;
            }
        #pragma unroll
        for (int o = 4; o <= 16; o <<= 1)
            #pragma unroll
            for (int q = 0; q < 16; q++) {
                float om = __shfl_xor_sync(0xffffffffu, cm[q], o);
                float os = __shfl_xor_sync(0xffffffffu, cs[q], o);
                msmerge(cm[q], cs[q], om, os);
            }
        if (gid == 0) {
            #pragma unroll
            for (int q = 0; q < 16; q++) {
                int col = n0 + wn * 64 + (q >> 1) * 8 + tig * 2 + (q & 1);
                size_t o = ((size_t)z * 32 + blockIdx.x * 2 + wm) * (size_t)LRn + col;
                PcM[o] = cm[q]; PcS[o] = cs[q];
            }
        }
    }
}

// ============================================================================
// Stat merges
// ============================================================================
__global__ void k_merge_row() {
    int idx = blockIdx.x * 256 + threadIdx.x;          // over MC
    int b = idx >> 11, c = idx & (LCn - 1);
    float m = -1e30f, s = 0.f;
    #pragma unroll
    for (int j = 0; j < 8; j++) {
        size_t o = ((size_t)b * 8 + j) * LCn + c;
        float nm = fmaxf(m, g_prM[o]);
        s = s * __expf(m - nm) + g_prS[o] * __expf(g_prM[o] - nm);
        m = nm;
    }
    g_amax[idx] = m; g_asum[idx] = s;
}

__global__ void k_merge_col() {
    int idx = blockIdx.x * 256 + threadIdx.x;          // over MR
    int b = idx >> 9, r = idx & (LRn - 1);
    float m = -1e30f, s = 0.f;
    #pragma unroll
    for (int j = 0; j < 32; j++) {
        size_t o = ((size_t)b * 32 + j) * LRn + r;
        float nm = fmaxf(m, g_pcM[o]);
        s = s * __expf(m - nm) + g_pcS[o] * __expf(g_pcM[o] - nm);
        m = nm;
    }
    g_bmax[idx] = m; g_bsum[idx] = s;
}

// ============================================================================
// Fused exp pass: one read of E -> EH/EL (row-normalized) + ETH/ETL (col-norm,
// transposed).
// ============================================================================
__global__ void k_expboth() {
    __shared__ float t[32][33];
    int z = blockIdx.z;
    int r0 = blockIdx.x * 32, c0 = blockIdx.y * 32;
    int x = threadIdx.x, y = threadIdx.y;
    const float* src = g_E + (size_t)z * LCn * LRn;
    #pragma unroll
    for (int i = 0; i < 32; i += 8) {
        int c = c0 + y + i;
        float v = src[(size_t)c * LRn + r0 + x];
        t[y + i][x] = v;
        float e = __expf(v - g_amax[z * LCn + c]);
        bf16 h, l; bsplit(e, h, l);
        size_t o = (size_t)z * LCn * LRn + (size_t)c * LRn + r0 + x;
        g_EH[o] = h; g_EL[o] = l;
    }
    __syncthreads();
    #pragma unroll
    for (int i = 0; i < 32; i += 8) {
        int r = r0 + y + i;
        float e = __expf(t[x][y + i] - g_bmax[z * LRn + r]);
        bf16 h, l; bsplit(e, h, l);
        size_t o = (size_t)z * LRn * LCn + (size_t)r * LCn + c0 + x;
        g_ETH[o] = h; g_ETL[o] = l;
    }
}

// ============================================================================
// Preprocessing
// ============================================================================
__global__ void k_split(const float* __restrict__ src, bf16* __restrict__ H,
                        bf16* __restrict__ L) {
    size_t e4 = ((size_t)blockIdx.x * 256 + threadIdx.x) * 4;
    float4 v = *(const float4*)(src + e4);
    bf16 h, l; __nv_bfloat162 h01, h23, l01, l23;
    bsplit(v.x, h, l); h01.x = h; l01.x = l;
    bsplit(v.y, h, l); h01.y = h; l01.y = l;
    bsplit(v.z, h, l); h23.x = h; l23.x = l;
    bsplit(v.w, h, l); h23.y = h; l23.y = l;
    *(__nv_bfloat162*)(H + e4) = h01; *(__nv_bfloat162*)(H + e4 + 2) = h23;
    *(__nv_bfloat162*)(L + e4) = l01; *(__nv_bfloat162*)(L + e4 + 2) = l23;
}

__global__ void k_tsplit(const float* __restrict__ src, bf16* __restrict__ H,
                         bf16* __restrict__ L, int rows, int cols) {
    __shared__ float t[32][33];
    int b = blockIdx.z;
    const float* s = src + (size_t)b * rows * cols;
    int c0 = blockIdx.x * 32, r0 = blockIdx.y * 32;
    int x = threadIdx.x, y = threadIdx.y;
    #pragma unroll
    for (int i = 0; i < 32; i += 8)
        t[y + i][x] = s[(size_t)(r0 + y + i) * cols + c0 + x];
    __syncthreads();
    #pragma unroll
    for (int i = 0; i < 32; i += 8) {
        float v = t[x][y + i];
        bf16 h, l; bsplit(v, h, l);
        size_t o = (size_t)b * rows * cols + (size_t)(c0 + y + i) * rows + r0 + x;
        H[o] = h; L[o] = l;
    }
}

__global__ void k_wcomb_split(const float* __restrict__ W1, const float* __restrict__ W2) {
    int i = blockIdx.x * 256 + threadIdx.x;
    if (i >= Hn * Dn) return;
    int hh = i >> 8, d = i & (Dn - 1);
    const float* w1 = W1 + (size_t)hh * 4 * Dn;
    const float* w2 = W2 + (size_t)hh * 4 * Dn;
    float v; bf16 h, l;
    size_t base = (size_t)hh * 3 * Dn + d;
    v = w1[d] + w1[2 * Dn + d];      bsplit(v, h, l); g_W1H[base] = h;          g_W1L[base] = l;
    v = w1[Dn + d] - w1[2 * Dn + d]; bsplit(v, h, l); g_W1H[base + Dn] = h;     g_W1L[base + Dn] = l;
    v = w1[3 * Dn + d];              bsplit(v, h, l); g_W1H[base + 2 * Dn] = h; g_W1L[base + 2 * Dn] = l;
    v = w2[d] + w2[2 * Dn + d];      bsplit(v, h, l); g_W2H[base] = h;          g_W2L[base] = l;
    v = w2[Dn + d] - w2[2 * Dn + d]; bsplit(v, h, l); g_W2H[base + Dn] = h;     g_W2L[base + Dn] = l;
    v = w2[3 * Dn + d];              bsplit(v, h, l); g_W2H[base + 2 * Dn] = h; g_W2L[base + 2 * Dn] = l;
}

// ============================================================================
extern "C" void kernel_launch(void* const* d_in, const int* in_sizes, int n_in,
                              void* d_out, int out_size) {
    const float* cs = (const float*)d_in[0];
    const float* rs = (const float*)d_in[1];
    const float* W1 = (const float*)d_in[2];
    const float* b1 = (const float*)d_in[3];
    const float* W2 = (const float*)d_in[4];
    const float* b2 = (const float*)d_in[5];
    float* cl = (float*)d_out;
    float* rl = cl + (size_t)MC * Hn;

    float* gE;  cudaGetSymbolAddress((void**)&gE,  g_E);
    bf16 *eH, *eL, *etH, *etL, *csH, *csL, *rsH, *rsL, *ctH, *ctL, *rtH, *rtL;
    bf16 *cdH, *cdL, *pcH, *pcL, *rdH, *rdL, *prH, *prL, *w1H, *w1L, *w2H, *w2L;
    cudaGetSymbolAddress((void**)&eH, g_EH);   cudaGetSymbolAddress((void**)&eL, g_EL);
    cudaGetSymbolAddress((void**)&etH, g_ETH); cudaGetSymbolAddress((void**)&etL, g_ETL);
    cudaGetSymbolAddress((void**)&csH, g_csH); cudaGetSymbolAddress((void**)&csL, g_csL);
    cudaGetSymbolAddress((void**)&rsH, g_rsH); cudaGetSymbolAddress((void**)&rsL, g_rsL);
    cudaGetSymbolAddress((void**)&ctH, g_csTH); cudaGetSymbolAddress((void**)&ctL, g_csTL);
    cudaGetSymbolAddress((void**)&rtH, g_rsTH); cudaGetSymbolAddress((void**)&rtL, g_rsTL);
    cudaGetSymbolAddress((void**)&cdH, g_cdH); cudaGetSymbolAddress((void**)&cdL, g_cdL);
    cudaGetSymbolAddress((void**)&pcH, g_pcH); cudaGetSymbolAddress((void**)&pcL, g_pcL);
    cudaGetSymbolAddress((void**)&rdH, g_rdH); cudaGetSymbolAddress((void**)&rdL, g_rdL);
    cudaGetSymbolAddress((void**)&prH, g_prH); cudaGetSymbolAddress((void**)&prL, g_prL);
    cudaGetSymbolAddress((void**)&w1H, g_W1H); cudaGetSymbolAddress((void**)&w1L, g_W1L);
    cudaGetSymbolAddress((void**)&w2H, g_W2H); cudaGetSymbolAddress((void**)&w2L, g_W2L);
    float *gas, *gbs, *prM, *prS, *pcM, *pcS;
    cudaGetSymbolAddress((void**)&gas, g_asum);
    cudaGetSymbolAddress((void**)&gbs, g_bsum);
    cudaGetSymbolAddress((void**)&prM, g_prM); cudaGetSymbolAddress((void**)&prS, g_prS);
    cudaGetSymbolAddress((void**)&pcM, g_pcM); cudaGetSymbolAddress((void**)&pcS, g_pcS);

    cudaFuncSetAttribute(k_gemm<0>, cudaFuncAttributeMaxDynamicSharedMemorySize, SMEM_DYN);
    cudaFuncSetAttribute(k_gemm<1>, cudaFuncAttributeMaxDynamicSharedMemorySize, SMEM_DYN);
    cudaFuncSetAttribute(k_gemm<2>, cudaFuncAttributeMaxDynamicSharedMemorySize, SMEM_DYN);

    k_wcomb_split<<<(Hn * Dn + 255) / 256, 256>>>(W1, W2);
    k_split<<<(int)((size_t)MC * Dn / 1024), 256>>>(cs, csH, csL);
    k_split<<<(int)((size_t)MR * Dn / 1024), 256>>>(rs, rsH, rsL);
    k_tsplit<<<dim3(8, 16, Bn), dim3(32, 8)>>>(rs, rtH, rtL, LRn, Dn);
    k_tsplit<<<dim3(8, 64, Bn), dim3(32, 8)>>>(cs, ctH, ctL, LCn, Dn);

    // E = cs * rs^T  (fp32 out + softmax partials)
    k_gemm<0><<<dim3(16, 4, Bn), 128, SMEM_DYN>>>(
        csH, csL, csH, csL, csH, csL, rsH, rsL,
        nullptr, nullptr, nullptr, gE, nullptr, nullptr, nullptr, nullptr,
        prM, prS, pcM, pcS,
        Dn, Dn, Dn, LRn,
        (size_t)LCn * Dn, (size_t)LRn * Dn, (size_t)LCn * LRn, 0);

    k_merge_row<<<MC / 256, 256>>>();
    k_merge_col<<<MR / 256, 256>>>();
    k_expboth<<<dim3(16, 64, Bn), dim3(32, 8)>>>();

    // cd(+pairs+prod): A = exp-split E (K=512), B = rsT pair
    k_gemm<1><<<dim3(16, 2, Bn), 128, SMEM_DYN>>>(
        eH, eL, eH, eL, eH, eL, rtH, rtL,
        gas, cs, nullptr, nullptr, cdH, cdL, pcH, pcL,
        nullptr, nullptr, nullptr, nullptr,
        LRn, LRn, LRn, Dn,
        (size_t)LCn * LRn, (size_t)Dn * LRn, (size_t)LCn * Dn, LCn);

    // rd(+pairs+prod): A = exp-split E^T (K=2048), B = csT pair
    k_gemm<1><<<dim3(4, 2, Bn), 128, SMEM_DYN>>>(
        etH, etL, etH, etL, etH, etL, ctH, ctL,
        gbs, rs, nullptr, nullptr, rdH, rdL, prH, prL,
        nullptr, nullptr, nullptr, nullptr,
        LCn, LCn, LCn, Dn,
        (size_t)LRn * LCn, (size_t)Dn * LCn, (size_t)LRn * Dn, LRn);

    // cl = relu([cs|cd|cs*cd] * W1c^T + b1)
    k_gemm<2><<<dim3(MC / 128, 1, 1), 128, SMEM_DYN>>>(
        csH, csL, cdH, cdL, pcH, pcL, w1H, w1L,
        nullptr, nullptr, b1, cl, nullptr, nullptr, nullptr, nullptr,
        nullptr, nullptr, nullptr, nullptr,
        3 * Dn, Dn, 3 * Dn, Hn, 0, 0, 0, 0);

    // rl = relu([rs|rd|rs*rd] * W2c^T + b2)
    k_gemm<2><<<dim3(MR / 128, 1, 1), 128, SMEM_DYN>>>(
        rsH, rsL, rdH, rdL, prH, prL, w2H, w2L,
        nullptr, nullptr, b2, rl, nullptr, nullptr, nullptr, nullptr,
        nullptr, nullptr, nullptr, nullptr,
        3 * Dn, Dn, 3 * Dn, Hn, 0, 0, 0, 0);
}

// round 11
// speedup vs baseline: 1.5031x; 1.0139x over previous
#include <cuda_runtime.h>
#include <cuda_bf16.h>
#include <math.h>
#include <stdint.h>

#define Bn  32
#define LCn 2048
#define LRn 512
#define Dn  256
#define Hn  128
#define MC  (Bn * LCn)
#define MR  (Bn * LRn)

typedef __nv_bfloat16 bf16;

// -------- scratch --------
static __device__ float g_E [(size_t)Bn * LCn * LRn];            // fp32 scores
static __device__ bf16 g_EH [(size_t)Bn * LCn * LRn], g_EL [(size_t)Bn * LCn * LRn];
static __device__ bf16 g_ETH[(size_t)Bn * LRn * LCn], g_ETL[(size_t)Bn * LRn * LCn];
static __device__ bf16 g_csH[(size_t)Bn * LCn * Dn],  g_csL[(size_t)Bn * LCn * Dn];
static __device__ bf16 g_rsH[(size_t)Bn * LRn * Dn],  g_rsL[(size_t)Bn * LRn * Dn];
static __device__ bf16 g_csTH[(size_t)Bn * Dn * LCn], g_csTL[(size_t)Bn * Dn * LCn];
static __device__ bf16 g_rsTH[(size_t)Bn * Dn * LRn], g_rsTL[(size_t)Bn * Dn * LRn];
static __device__ bf16 g_cdH[(size_t)Bn * LCn * Dn],  g_cdL[(size_t)Bn * LCn * Dn];
static __device__ bf16 g_pcH[(size_t)Bn * LCn * Dn],  g_pcL[(size_t)Bn * LCn * Dn];
static __device__ bf16 g_rdH[(size_t)Bn * LRn * Dn],  g_rdL[(size_t)Bn * LRn * Dn];
static __device__ bf16 g_prH[(size_t)Bn * LRn * Dn],  g_prL[(size_t)Bn * LRn * Dn];
static __device__ bf16 g_W1H[Hn * 3 * Dn], g_W1L[Hn * 3 * Dn];
static __device__ bf16 g_W2H[Hn * 3 * Dn], g_W2L[Hn * 3 * Dn];
static __device__ float g_amax[MC], g_asum[MC];
static __device__ float g_bmax[MR], g_bsum[MR];
static __device__ float g_prM[(size_t)Bn * 8 * LCn], g_prS[(size_t)Bn * 8 * LCn];
static __device__ float g_pcM[(size_t)Bn * 32 * LRn], g_pcS[(size_t)Bn * 32 * LRn];

// ======================== helpers =============================
__device__ __forceinline__ uint32_t smem_u32(const void* p) {
    uint32_t a;
    asm("{ .reg .u64 t; cvta.to.shared.u64 t, %1; cvt.u32.u64 %0, t; }" : "=r"(a) : "l"(p));
    return a;
}

#define LDSM4(r, addr) \
    asm volatile("ldmatrix.sync.aligned.m8n8.x4.shared.b16 {%0,%1,%2,%3}, [%4];" \
        : "=r"((r)[0]), "=r"((r)[1]), "=r"((r)[2]), "=r"((r)[3]) : "r"(addr))

#define MMA_BF16(c, a, b0, b1) \
    asm volatile("mma.sync.aligned.m16n8k16.row.col.f32.bf16.bf16.f32 " \
        "{%0,%1,%2,%3}, {%4,%5,%6,%7}, {%8,%9}, {%0,%1,%2,%3};" \
        : "+f"((c)[0]), "+f"((c)[1]), "+f"((c)[2]), "+f"((c)[3]) \
        : "r"((a)[0]), "r"((a)[1]), "r"((a)[2]), "r"((a)[3]), "r"(b0), "r"(b1))

#define CP16(dst, src) \
    asm volatile("cp.async.cg.shared.global [%0], [%1], 16;" :: "r"(dst), "l"(src))
#define CP_COMMIT() asm volatile("cp.async.commit_group;" ::: "memory")
#define CP_WAIT(n)  asm volatile("cp.async.wait_group %0;" :: "n"(n) : "memory")

__device__ __forceinline__ void bsplit(float v, bf16& h, bf16& l) {
    h = __float2bfloat16(v);
    l = __float2bfloat16(v - __bfloat162float(h));
}

__device__ __forceinline__ void msmerge(float& m, float& s, float om, float os) {
    float nm = fmaxf(m, om);
    s = s * __expf(m - nm) + os * __expf(om - nm);
    m = nm;
}

// smem tile: [rows][32 k] bf16, row = 64B = 4x16B units; conflict-free swizzle.
__device__ __forceinline__ uint32_t toff16(int row, int u) {
    return (row << 6) + ((u ^ ((row >> 1) & 3)) << 4);
}

// stage: A 128x32 (H,L) + B 128x32 (H,L) = 32 KB
#define SM_AH 0
#define SM_AL 8192
#define SM_BH 16384
#define SM_BL 24576
#define STAGE_B 32768
#define SMEM_DYN (3 * STAGE_B)

// ============================================================================
// Unified NT GEMM on pre-split bf16 pairs: C[128,128] = A[128,K]*B[128,K]^T
// (3 products HH+HL+LH).  EPI 0: fp32 + softmax partial stats.
// EPI 1: scale 1/rsum, emit split pairs + split(X*scaled).  EPI 2: relu+bias.
// 128 threads, 4 warps (2x2, 64x64 each), 3-stage cp.async, 2 CTAs/SM.
// Mainloop: mid-chunk barrier; next-chunk A-fragments hoisted across it.
// ============================================================================
template<int EPI>
__global__ void __launch_bounds__(128, 2) k_gemm(
    const bf16* __restrict__ AH0, const bf16* __restrict__ AL0,
    const bf16* __restrict__ AH1, const bf16* __restrict__ AL1,
    const bf16* __restrict__ AH2, const bf16* __restrict__ AL2,
    const bf16* __restrict__ BH,  const bf16* __restrict__ BL,
    const float* __restrict__ rsum, const float* __restrict__ Xf,
    const float* __restrict__ bias, float* __restrict__ Cf,
    bf16* __restrict__ CoH, bf16* __restrict__ CoL,
    bf16* __restrict__ PoH, bf16* __restrict__ PoL,
    float* __restrict__ PrM, float* __restrict__ PrS,
    float* __restrict__ PcM, float* __restrict__ PcS,
    int K, int lda, int ldb, int ldc,
    size_t aB, size_t bB, size_t cB, int sB)
{
    extern __shared__ __align__(16) uint8_t sm[];
    const uint32_t sb = smem_u32(sm);
    const int tid = threadIdx.x;
    const int z = blockIdx.z;
    const int m0 = blockIdx.x * 128, n0 = blockIdx.y * 128;
    const bf16* aH0 = AH0 + (size_t)z * aB;
    const bf16* aL0 = AL0 + (size_t)z * aB;
    const bf16* bH  = BH  + (size_t)z * bB;
    const bf16* bL  = BL  + (size_t)z * bB;

    const int lane = tid & 31, wid = tid >> 5;
    const int wm = wid & 1, wn = wid >> 1;        // 2x2 warps, 64x64 each
    const int gid = lane >> 2, tig = lane & 3;

    float acc[4][8][4];
    #pragma unroll
    for (int a = 0; a < 4; a++)
        #pragma unroll
        for (int b = 0; b < 8; b++)
            #pragma unroll
            for (int c = 0; c < 4; c++) acc[a][b][c] = 0.f;

    const int S = K >> 5;

    auto cp_stage = [&](int buf, int kc) {
        const uint32_t tb = sb + buf * STAGE_B;
        const int k0 = kc << 5;
        const bf16* aH = aH0; const bf16* aL = aL0;
        int kk = k0;
        if (EPI == 2) {
            int seg = k0 >> 8; kk = k0 & 255;
            if (seg == 1) { aH = AH1; aL = AL1; }
            else if (seg == 2) { aH = AH2; aL = AL2; }
        }
        #pragma unroll
        for (int i = 0; i < 4; i++) {
            int idx = tid + i * 128;
            int row = idx >> 2, u = idx & 3;
            uint32_t off = toff16(row, u);
            const size_t g = (size_t)(m0 + row) * lda + kk + u * 8;
            CP16(tb + SM_AH + off, aH + g);
            CP16(tb + SM_AL + off, aL + g);
        }
        #pragma unroll
        for (int i = 0; i < 4; i++) {
            int idx = tid + i * 128;
            int row = idx >> 2, u = idx & 3;
            uint32_t off = toff16(row, u);
            const size_t g = (size_t)(n0 + row) * ldb + k0 + u * 8;
            CP16(tb + SM_BH + off, bH + g);
            CP16(tb + SM_BL + off, bL + g);
        }
    };

    // A-fragment loader for one k16 half
    auto ldA = [&](uint32_t tb, int kb, uint32_t (&ah)[4][4], uint32_t (&al)[4][4]) {
        #pragma unroll
        for (int mb = 0; mb < 4; mb++) {
            int row = wm * 64 + mb * 16 + (lane & 15);
            uint32_t off = toff16(row, kb * 2 + (lane >> 4));
            LDSM4(ah[mb], tb + SM_AH + off);
            LDSM4(al[mb], tb + SM_AL + off);
        }
    };

    // MMAs for one k16 half (B frags streamed per np)
    auto mmaHalf = [&](uint32_t tb, int kb, uint32_t (&ah)[4][4], uint32_t (&al)[4][4]) {
        #pragma unroll
        for (int np = 0; np < 4; np++) {
            int nrow = wn * 64 + np * 16 + (lane & 7) + ((lane >> 4) << 3);
            uint32_t off = toff16(nrow, kb * 2 + ((lane >> 3) & 1));
            uint32_t bh[4], bl[4];
            LDSM4(bh, tb + SM_BH + off);
            LDSM4(bl, tb + SM_BL + off);
            #pragma unroll
            for (int nb = 0; nb < 2; nb++)
                #pragma unroll
                for (int mb = 0; mb < 4; mb++)
                    MMA_BF16(acc[mb][np*2+nb], ah[mb], bh[nb*2], bh[nb*2+1]);
            #pragma unroll
            for (int nb = 0; nb < 2; nb++)
                #pragma unroll
                for (int mb = 0; mb < 4; mb++)
                    MMA_BF16(acc[mb][np*2+nb], ah[mb], bl[nb*2], bl[nb*2+1]);
            #pragma unroll
            for (int nb = 0; nb < 2; nb++)
                #pragma unroll
                for (int mb = 0; mb < 4; mb++)
                    MMA_BF16(acc[mb][np*2+nb], al[mb], bh[nb*2], bh[nb*2+1]);
        }
    };

    uint32_t A0h[4][4], A0l[4][4], A1h[4][4], A1l[4][4];

    cp_stage(0, 0); CP_COMMIT();
    if (S > 1) cp_stage(1, 1);
    CP_COMMIT();
    CP_WAIT(1);
    __syncthreads();                  // stage 0 visible
    ldA(sb, 0, A0h, A0l);

    for (int s = 0; s < S; s++) {
        const uint32_t tb = sb + (s % 3) * STAGE_B;
        ldA(tb, 1, A1h, A1l);         // kb1 frags hide under kb0 MMAs
        mmaHalf(tb, 0, A0h, A0l);

        CP_WAIT(0);                   // stage s+1 arrived (per-thread)
        __syncthreads();              // all threads: stage s+1 visible; all done
                                      // reading the buffer cp below overwrites
        if (s + 2 < S) cp_stage((s + 2) % 3, s + 2);
        CP_COMMIT();
        if (s + 1 < S) {              // next chunk's kb0 frags hide under kb1 MMAs
            const uint32_t tbn = sb + ((s + 1) % 3) * STAGE_B;
            ldA(tbn, 0, A0h, A0l);
        }
        mmaHalf(tb, 1, A1h, A1l);
    }

    // ---- epilogue ----
    #pragma unroll
    for (int mb = 0; mb < 4; mb++) {
        int r0 = m0 + wm * 64 + mb * 16 + gid;
        int r1 = r0 + 8;
        float s0 = 1.f, s1 = 1.f;
        if (EPI == 1) {
            s0 = 1.0f / rsum[(size_t)z * sB + r0];
            s1 = 1.0f / rsum[(size_t)z * sB + r1];
        }
        #pragma unroll
        for (int nb = 0; nb < 8; nb++) {
            int col = n0 + wn * 64 + nb * 8 + tig * 2;
            float c0 = acc[mb][nb][0], c1 = acc[mb][nb][1];
            float c2 = acc[mb][nb][2], c3 = acc[mb][nb][3];
            if (EPI == 0) {
                float* C = Cf + (size_t)z * cB;
                *(float2*)(C + (size_t)r0 * ldc + col) = make_float2(c0, c1);
                *(float2*)(C + (size_t)r1 * ldc + col) = make_float2(c2, c3);
            } else if (EPI == 2) {
                float b0v = bias[col], b1v = bias[col + 1];
                float* C = Cf;
                *(float2*)(C + (size_t)r0 * ldc + col) =
                    make_float2(fmaxf(c0 + b0v, 0.f), fmaxf(c1 + b1v, 0.f));
                *(float2*)(C + (size_t)r1 * ldc + col) =
                    make_float2(fmaxf(c2 + b0v, 0.f), fmaxf(c3 + b1v, 0.f));
            } else {
                c0 *= s0; c1 *= s0; c2 *= s1; c3 *= s1;
                const float* X = Xf + (size_t)z * cB;
                bf16* cH = CoH + (size_t)z * cB; bf16* cL = CoL + (size_t)z * cB;
                bf16* pH = PoH + (size_t)z * cB; bf16* pL = PoL + (size_t)z * cB;
                size_t o0 = (size_t)r0 * ldc + col, o1 = (size_t)r1 * ldc + col;
                float2 x0 = *(const float2*)(X + o0);
                float2 x1 = *(const float2*)(X + o1);
                bf16 h, l; __nv_bfloat162 hv, lv;
                bsplit(c0, h, l); hv.x = h; lv.x = l;
                bsplit(c1, h, l); hv.y = h; lv.y = l;
                *(__nv_bfloat162*)(cH + o0) = hv; *(__nv_bfloat162*)(cL + o0) = lv;
                bsplit(c2, h, l); hv.x = h; lv.x = l;
                bsplit(c3, h, l); hv.y = h; lv.y = l;
                *(__nv_bfloat162*)(cH + o1) = hv; *(__nv_bfloat162*)(cL + o1) = lv;
                bsplit(x0.x * c0, h, l); hv.x = h; lv.x = l;
                bsplit(x0.y * c1, h, l); hv.y = h; lv.y = l;
                *(__nv_bfloat162*)(pH + o0) = hv; *(__nv_bfloat162*)(pL + o0) = lv;
                bsplit(x1.x * c2, h, l); hv.x = h; lv.x = l;
                bsplit(x1.y * c3, h, l); hv.y = h; lv.y = l;
                *(__nv_bfloat162*)(pH + o1) = hv; *(__nv_bfloat162*)(pL + o1) = lv;
            }
        }
    }

    // ---- EPI 0: softmax partial stats from live accumulators ----
    if (EPI == 0) {
        float rm[8], rs[8];
        #pragma unroll
        for (int mb = 0; mb < 4; mb++)
            #pragma unroll
            for (int h = 0; h < 2; h++) {
                float m = -1e30f;
                #pragma unroll
                for (int nb = 0; nb < 8; nb++)
                    m = fmaxf(m, fmaxf(acc[mb][nb][h*2], acc[mb][nb][h*2+1]));
                float ss = 0.f;
                #pragma unroll
                for (int nb = 0; nb < 8; nb++)
                    ss += __expf(acc[mb][nb][h*2] - m) + __expf(acc[mb][nb][h*2+1] - m);
                rm[mb*2+h] = m; rs[mb*2+h] = ss;
            }
        #pragma unroll
        for (int o = 1; o <= 2; o <<= 1)
            #pragma unroll
            for (int j = 0; j < 8; j++) {
                float om = __shfl_xor_sync(0xffffffffu, rm[j], o);
                float os = __shfl_xor_sync(0xffffffffu, rs[j], o);
                msmerge(rm[j], rs[j], om, os);
            }
        if (tig == 0) {
            #pragma unroll
            for (int j = 0; j < 8; j++) {
                int row = m0 + wm * 64 + (j >> 1) * 16 + (j & 1) * 8 + gid;
                size_t o = ((size_t)z * 8 + blockIdx.y * 2 + wn) * (size_t)LCn + row;
                PrM[o] = rm[j]; PrS[o] = rs[j];
            }
        }
        float cm[16], cs[16];
        #pragma unroll
        for (int nb = 0; nb < 8; nb++)
            #pragma unroll
            for (int j = 0; j < 2; j++) {
                float m = -1e30f;
                #pragma unroll
                for (int mb = 0; mb < 4; mb++)
                    m = fmaxf(m, fmaxf(acc[mb][nb][j], acc[mb][nb][j+2]));
                float ss = 0.f;
                #pragma unroll
                for (int mb = 0; mb < 4; mb++)
                    ss += __expf(acc[mb][nb][j] - m) + __expf(acc[mb][nb][j+2] - m);
                cm[nb*2+j] = m; cs[nb*2+j] = ss;
            }
        #pragma unroll
        for (int o = 4; o <= 16; o <<= 1)
            #pragma unroll
            for (int q = 0; q < 16; q++) {
                float om = __shfl_xor_sync(0xffffffffu, cm[q], o);
                float os = __shfl_xor_sync(0xffffffffu, cs[q], o);
                msmerge(cm[q], cs[q], om, os);
            }
        if (gid == 0) {
            #pragma unroll
            for (int q = 0; q < 16; q++) {
                int col = n0 + wn * 64 + (q >> 1) * 8 + tig * 2 + (q & 1);
                size_t o = ((size_t)z * 32 + blockIdx.x * 2 + wm) * (size_t)LRn + col;
                PcM[o] = cm[q]; PcS[o] = cs[q];
            }
        }
    }
}

// ============================================================================
// Stat merges
// ============================================================================
__global__ void k_merge_row() {
    int idx = blockIdx.x * 256 + threadIdx.x;
    int b = idx >> 11, c = idx & (LCn - 1);
    float m = -1e30f, s = 0.f;
    #pragma unroll
    for (int j = 0; j < 8; j++) {
        size_t o = ((size_t)b * 8 + j) * LCn + c;
        float nm = fmaxf(m, g_prM[o]);
        s = s * __expf(m - nm) + g_prS[o] * __expf(g_prM[o] - nm);
        m = nm;
    }
    g_amax[idx] = m; g_asum[idx] = s;
}

__global__ void k_merge_col() {
    int idx = blockIdx.x * 256 + threadIdx.x;
    int b = idx >> 9, r = idx & (LRn - 1);
    float m = -1e30f, s = 0.f;
    #pragma unroll
    for (int j = 0; j < 32; j++) {
        size_t o = ((size_t)b * 32 + j) * LRn + r;
        float nm = fmaxf(m, g_pcM[o]);
        s = s * __expf(m - nm) + g_pcS[o] * __expf(g_pcM[o] - nm);
        m = nm;
    }
    g_bmax[idx] = m; g_bsum[idx] = s;
}

// ============================================================================
// Fused exp pass: one read of E -> EH/EL (row-norm) + ETH/ETL (col-norm, T).
// ============================================================================
__global__ void k_expboth() {
    __shared__ float t[32][33];
    int z = blockIdx.z;
    int r0 = blockIdx.x * 32, c0 = blockIdx.y * 32;
    int x = threadIdx.x, y = threadIdx.y;
    const float* src = g_E + (size_t)z * LCn * LRn;
    #pragma unroll
    for (int i = 0; i < 32; i += 8) {
        int c = c0 + y + i;
        float v = src[(size_t)c * LRn + r0 + x];
        t[y + i][x] = v;
        float e = __expf(v - g_amax[z * LCn + c]);
        bf16 h, l; bsplit(e, h, l);
        size_t o = (size_t)z * LCn * LRn + (size_t)c * LRn + r0 + x;
        g_EH[o] = h; g_EL[o] = l;
    }
    __syncthreads();
    #pragma unroll
    for (int i = 0; i < 32; i += 8) {
        int r = r0 + y + i;
        float e = __expf(t[x][y + i] - g_bmax[z * LRn + r]);
        bf16 h, l; bsplit(e, h, l);
        size_t o = (size_t)z * LRn * LCn + (size_t)r * LCn + c0 + x;
        g_ETH[o] = h; g_ETL[o] = l;
    }
}

// ============================================================================
// Fused preprocessing: one read of src -> split (H,L) + transposed split.
// ============================================================================
__global__ void k_splitboth(const float* __restrict__ src,
                            bf16* __restrict__ H,  bf16* __restrict__ L,
                            bf16* __restrict__ HT, bf16* __restrict__ LT,
                            int rows, int cols) {
    __shared__ float t[32][33];
    int b = blockIdx.z;
    const float* s = src + (size_t)b * rows * cols;
    size_t base = (size_t)b * rows * cols;
    int c0 = blockIdx.x * 32, r0 = blockIdx.y * 32;
    int x = threadIdx.x, y = threadIdx.y;
    #pragma unroll
    for (int i = 0; i < 32; i += 8) {
        int row = r0 + y + i;
        float v = s[(size_t)row * cols + c0 + x];
        t[y + i][x] = v;
        bf16 h, l; bsplit(v, h, l);
        size_t o = base + (size_t)row * cols + c0 + x;
        H[o] = h; L[o] = l;
    }
    __syncthreads();
    #pragma unroll
    for (int i = 0; i < 32; i += 8) {
        float v = t[x][y + i];
        bf16 h, l; bsplit(v, h, l);
        size_t o = base + (size_t)(c0 + y + i) * rows + r0 + x;
        HT[o] = h; LT[o] = l;
    }
}

__global__ void k_wcomb_split(const float* __restrict__ W1, const float* __restrict__ W2) {
    int i = blockIdx.x * 256 + threadIdx.x;
    if (i >= Hn * Dn) return;
    int hh = i >> 8, d = i & (Dn - 1);
    const float* w1 = W1 + (size_t)hh * 4 * Dn;
    const float* w2 = W2 + (size_t)hh * 4 * Dn;
    float v; bf16 h, l;
    size_t base = (size_t)hh * 3 * Dn + d;
    v = w1[d] + w1[2 * Dn + d];      bsplit(v, h, l); g_W1H[base] = h;          g_W1L[base] = l;
    v = w1[Dn + d] - w1[2 * Dn + d]; bsplit(v, h, l); g_W1H[base + Dn] = h;     g_W1L[base + Dn] = l;
    v = w1[3 * Dn + d];              bsplit(v, h, l); g_W1H[base + 2 * Dn] = h; g_W1L[base + 2 * Dn] = l;
    v = w2[d] + w2[2 * Dn + d];      bsplit(v, h, l); g_W2H[base] = h;          g_W2L[base] = l;
    v = w2[Dn + d] - w2[2 * Dn + d]; bsplit(v, h, l); g_W2H[base + Dn] = h;     g_W2L[base + Dn] = l;
    v = w2[3 * Dn + d];              bsplit(v, h, l); g_W2H[base + 2 * Dn] = h; g_W2L[base + 2 * Dn] = l;
}

// ============================================================================
extern "C" void kernel_launch(void* const* d_in, const int* in_sizes, int n_in,
                              void* d_out, int out_size) {
    const float* cs = (const float*)d_in[0];
    const float* rs = (const float*)d_in[1];
    const float* W1 = (const float*)d_in[2];
    const float* b1 = (const float*)d_in[3];
    const float* W2 = (const float*)d_in[4];
    const float* b2 = (const float*)d_in[5];
    float* cl = (float*)d_out;
    float* rl = cl + (size_t)MC * Hn;

    float* gE;  cudaGetSymbolAddress((void**)&gE,  g_E);
    bf16 *eH, *eL, *etH, *etL, *csH, *csL, *rsH, *rsL, *ctH, *ctL, *rtH, *rtL;
    bf16 *cdH, *cdL, *pcH, *pcL, *rdH, *rdL, *prH, *prL, *w1H, *w1L, *w2H, *w2L;
    cudaGetSymbolAddress((void**)&eH, g_EH);   cudaGetSymbolAddress((void**)&eL, g_EL);
    cudaGetSymbolAddress((void**)&etH, g_ETH); cudaGetSymbolAddress((void**)&etL, g_ETL);
    cudaGetSymbolAddress((void**)&csH, g_csH); cudaGetSymbolAddress((void**)&csL, g_csL);
    cudaGetSymbolAddress((void**)&rsH, g_rsH); cudaGetSymbolAddress((void**)&rsL, g_rsL);
    cudaGetSymbolAddress((void**)&ctH, g_csTH); cudaGetSymbolAddress((void**)&ctL, g_csTL);
    cudaGetSymbolAddress((void**)&rtH, g_rsTH); cudaGetSymbolAddress((void**)&rtL, g_rsTL);
    cudaGetSymbolAddress((void**)&cdH, g_cdH); cudaGetSymbolAddress((void**)&cdL, g_cdL);
    cudaGetSymbolAddress((void**)&pcH, g_pcH); cudaGetSymbolAddress((void**)&pcL, g_pcL);
    cudaGetSymbolAddress((void**)&rdH, g_rdH); cudaGetSymbolAddress((void**)&rdL, g_rdL);
    cudaGetSymbolAddress((void**)&prH, g_prH); cudaGetSymbolAddress((void**)&prL, g_prL);
    cudaGetSymbolAddress((void**)&w1H, g_W1H); cudaGetSymbolAddress((void**)&w1L, g_W1L);
    cudaGetSymbolAddress((void**)&w2H, g_W2H); cudaGetSymbolAddress((void**)&w2L, g_W2L);
    float *gas, *gbs, *prM, *prS, *pcM, *pcS;
    cudaGetSymbolAddress((void**)&gas, g_asum);
    cudaGetSymbolAddress((void**)&gbs, g_bsum);
    cudaGetSymbolAddress((void**)&prM, g_prM); cudaGetSymbolAddress((void**)&prS, g_prS);
    cudaGetSymbolAddress((void**)&pcM, g_pcM); cudaGetSymbolAddress((void**)&pcS, g_pcS);

    cudaFuncSetAttribute(k_gemm<0>, cudaFuncAttributeMaxDynamicSharedMemorySize, SMEM_DYN);
    cudaFuncSetAttribute(k_gemm<1>, cudaFuncAttributeMaxDynamicSharedMemorySize, SMEM_DYN);
    cudaFuncSetAttribute(k_gemm<2>, cudaFuncAttributeMaxDynamicSharedMemorySize, SMEM_DYN);

    k_wcomb_split<<<(Hn * Dn + 255) / 256, 256>>>(W1, W2);
    k_splitboth<<<dim3(8, 16, Bn), dim3(32, 8)>>>(rs, rsH, rsL, rtH, rtL, LRn, Dn);
    k_splitboth<<<dim3(8, 64, Bn), dim3(32, 8)>>>(cs, csH, csL, ctH, ctL, LCn, Dn);

    // E = cs * rs^T  (fp32 out + softmax partials)
    k_gemm<0><<<dim3(16, 4, Bn), 128, SMEM_DYN>>>(
        csH, csL, csH, csL, csH, csL, rsH, rsL,
        nullptr, nullptr, nullptr, gE, nullptr, nullptr, nullptr, nullptr,
        prM, prS, pcM, pcS,
        Dn, Dn, Dn, LRn,
        (size_t)LCn * Dn, (size_t)LRn * Dn, (size_t)LCn * LRn, 0);

    k_merge_row<<<MC / 256, 256>>>();
    k_merge_col<<<MR / 256, 256>>>();
    k_expboth<<<dim3(16, 64, Bn), dim3(32, 8)>>>();

    // cd(+pairs+prod): A = exp-split E (K=512), B = rsT pair
    k_gemm<1><<<dim3(16, 2, Bn), 128, SMEM_DYN>>>(
        eH, eL, eH, eL, eH, eL, rtH, rtL,
        gas, cs, nullptr, nullptr, cdH, cdL, pcH, pcL,
        nullptr, nullptr, nullptr, nullptr,
        LRn, LRn, LRn, Dn,
        (size_t)LCn * LRn, (size_t)Dn * LRn, (size_t)LCn * Dn, LCn);

    // rd(+pairs+prod): A = exp-split E^T (K=2048), B = csT pair
    k_gemm<1><<<dim3(4, 2, Bn), 128, SMEM_DYN>>>(
        etH, etL, etH, etL, etH, etL, ctH, ctL,
        gbs, rs, nullptr, nullptr, rdH, rdL, prH, prL,
        nullptr, nullptr, nullptr, nullptr,
        LCn, LCn, LCn, Dn,
        (size_t)LRn * LCn, (size_t)Dn * LCn, (size_t)LRn * Dn, LRn);

    // cl = relu([cs|cd|cs*cd] * W1c^T + b1)
    k_gemm<2><<<dim3(MC / 128, 1, 1), 128, SMEM_DYN>>>(
        csH, csL, cdH, cdL, pcH, pcL, w1H, w1L,
        nullptr, nullptr, b1, cl, nullptr, nullptr, nullptr, nullptr,
        nullptr, nullptr, nullptr, nullptr,
        3 * Dn, Dn, 3 * Dn, Hn, 0, 0, 0, 0);

    // rl = relu([rs|rd|rs*rd] * W2c^T + b2)
    k_gemm<2><<<dim3(MR / 128, 1, 1), 128, SMEM_DYN>>>(
        rsH, rsL, rdH, rdL, prH, prL, w2H, w2L,
        nullptr, nullptr, b2, rl, nullptr, nullptr, nullptr, nullptr,
        nullptr, nullptr, nullptr, nullptr,
        3 * Dn, Dn, 3 * Dn, Hn, 0, 0, 0, 0);
}